// round 9
// baseline (speedup 1.0000x reference)
#include <cuda_runtime.h>
#include <cuda_bf16.h>
#include <cstdint>

#define SB 2
#define SS 8192
#define SH 8
#define SD 64
#define SC 32
#define SNW 768

#if defined(__CUDA_ARCH_FEAT_SM103_ALL) || defined(__CUDA_ARCH_FEAT_SM100_ALL) || \
    defined(__CUDA_ARCH_FEAT_SM101_ALL) || defined(__CUDA_ARCH_FEAT_SM110_ALL)
#define HAS_TC 1
#else
#define HAS_TC 0
#endif

// smem layout (bytes)
#define OFF_MBQ   8
#define OFF_MBP   16
#define OFF_RS    32
#define OFF_INV   1056
#define OFF_QHI   2048
#define OFF_QLO   18432
#define OFF_KHI   34816
#define OFF_KLO   51200
#define OFF_VHI   67584
#define OFF_VLO   83968
#define OFF_PHI   100352
#define OFF_PLO   133120
#define OFF_STG   165888
#define STG_STRIDE 36            /* floats; 144B row pitch = 16B-aligned */
#define STG_WG    18432
#define SMEM_TC   202752

#define IDESC_QK 0x08200490u   /* M=128 N=128 */
#define IDESC_PV 0x08100490u   /* M=128 N=64  */

#if HAS_TC
__device__ __forceinline__ uint32_t smem_u32(const void* p) {
    uint32_t a;
    asm("{ .reg .u64 t; cvta.to.shared.u64 t, %1; cvt.u32.u64 %0, t; }" : "=r"(a) : "l"(p));
    return a;
}
__device__ __forceinline__ uint32_t elect1() {
    uint32_t p;
    asm volatile("{ .reg .pred p; elect.sync _|p, 0xFFFFFFFF; selp.b32 %0, 1, 0, p; }" : "=r"(p));
    return p;
}
__device__ __forceinline__ uint64_t desc_k(uint32_t a) {   // K-major SW128: LBO=1, SBO=64
    return (2ull << 61) | (1ull << 46) | (64ull << 32) | (1ull << 16) | ((a >> 4) & 0x3FFF);
}
__device__ __forceinline__ void mma_ss(uint32_t d, uint64_t a, uint64_t b, uint32_t id, uint32_t en) {
    asm volatile(
        "{\n\t.reg .pred p;\n\tsetp.ne.u32 p, %4, 0;\n\t"
        "tcgen05.mma.cta_group::1.kind::f16 [%0], %1, %2, %3, {%5, %5, %5, %5}, p;\n\t}"
        :: "r"(d), "l"(a), "l"(b), "r"(id), "r"(en), "r"(0u) : "memory");
}
#define TM_FENCE_A() asm volatile("tcgen05.fence::after_thread_sync;" ::: "memory")
#define TM_FENCE_B() asm volatile("tcgen05.fence::before_thread_sync;" ::: "memory")
#define TM_WAIT_LD() asm volatile("tcgen05.wait::ld.sync.aligned;" ::: "memory")
#define FENCE_ASYNC() asm volatile("fence.proxy.async.shared::cta;" ::: "memory")
#define COMMIT(mb) asm volatile("tcgen05.commit.cta_group::1.mbarrier::arrive::one.shared::cluster.b64 [%0];" :: "r"(mb) : "memory")

#define MBAR_WAIT(mb, pa) do {                                                            \
    asm volatile("{\n\t.reg .pred P1;\n\t"                                                \
        "WL%=:\n\t"                                                                       \
        "mbarrier.try_wait.parity.acquire.cta.shared::cta.b64 P1, [%0], %1, 0x989680;\n\t"\
        "@P1 bra.uni WD%=;\n\t"                                                           \
        "bra.uni WL%=;\n\t"                                                               \
        "WD%=:\n\t}" :: "r"(mb), "r"(pa) : "memory");                                     \
} while (0)

#define LDTM_X32(r, a)                                                                    \
    asm volatile("tcgen05.ld.sync.aligned.32x32b.x32.b32 "                                \
        "{%0, %1, %2, %3, %4, %5, %6, %7, %8, %9, %10, %11, %12, %13, %14, %15, "         \
        " %16, %17, %18, %19, %20, %21, %22, %23, %24, %25, %26, %27, %28, %29, %30, %31}, [%32];" \
        : "=r"((r)[0]),  "=r"((r)[1]),  "=r"((r)[2]),  "=r"((r)[3]),                      \
          "=r"((r)[4]),  "=r"((r)[5]),  "=r"((r)[6]),  "=r"((r)[7]),                      \
          "=r"((r)[8]),  "=r"((r)[9]),  "=r"((r)[10]), "=r"((r)[11]),                     \
          "=r"((r)[12]), "=r"((r)[13]), "=r"((r)[14]), "=r"((r)[15]),                     \
          "=r"((r)[16]), "=r"((r)[17]), "=r"((r)[18]), "=r"((r)[19]),                     \
          "=r"((r)[20]), "=r"((r)[21]), "=r"((r)[22]), "=r"((r)[23]),                     \
          "=r"((r)[24]), "=r"((r)[25]), "=r"((r)[26]), "=r"((r)[27]),                     \
          "=r"((r)[28]), "=r"((r)[29]), "=r"((r)[30]), "=r"((r)[31])                      \
        : "r"(a))

__device__ __forceinline__ void split_pair(float a, float b, uint32_t& hi, uint32_t& lo) {
    uint32_t h;
    asm("cvt.rn.bf16x2.f32 %0, %1, %2;" : "=r"(h) : "f"(b), "f"(a));  // lo16=a, hi16=b
    float fa = __uint_as_float(h << 16);
    float fb = __uint_as_float(h & 0xffff0000u);
    uint32_t l;
    asm("cvt.rn.bf16x2.f32 %0, %1, %2;" : "=r"(l) : "f"(b - fb), "f"(a - fa));
    hi = h; lo = l;
}

// prefetch 128x64 fp32 tile into 8 float4 regs
__device__ __forceinline__ void ldg8(const float* __restrict__ g, bool valid, int tid, float4* r) {
    #pragma unroll
    for (int it = 0; it < 8; it++) {
        int i = it * 256 + tid;
        int n = i >> 4, e4 = (i & 15) << 2;
        r[it] = valid ? *(const float4*)(g + (size_t)n * (SH * SD) + e4)
                      : make_float4(0.f, 0.f, 0.f, 0.f);
    }
}
// regs -> bf16 hi/lo, K-major SW128 128B rows (Q and K tiles)
__device__ __forceinline__ void sts_split(const float4* r, char* smc, int offhi, int offlo, int tid) {
    #pragma unroll
    for (int it = 0; it < 8; it++) {
        int i = it * 256 + tid;
        int n = i >> 4, e4 = (i & 15) << 2;
        uint32_t h0, l0, h1, l1;
        split_pair(r[it].x, r[it].y, h0, l0);
        split_pair(r[it].z, r[it].w, h1, l1);
        int boff = n * 128 + e4 * 2;
        int sw = boff ^ ((boff >> 3) & 0x70);
        *(uint2*)(smc + offhi + sw) = make_uint2(h0, h1);
        *(uint2*)(smc + offlo + sw) = make_uint2(l0, l1);
    }
}

// ---- V^T path: conflict-free transpose ----
// warp w, iter i(0..15): dim e = w*8 + (i&7); atom-col ac = i>>3.
// lane: token-pair u = lane ^ (4*(e&7))  -> smem bank == lane (conflict-free).
__device__ __forceinline__ void ldg_vt(const float* __restrict__ g, bool valid,
                                       int w, int lane, float2* r) {
    #pragma unroll
    for (int i = 0; i < 16; i++) {
        int e = w * 8 + (i & 7);
        int u = lane ^ (4 * (e & 7));
        int n0 = (i >> 3) * 64 + 2 * u;
        float a = 0.f, bb = 0.f;
        if (valid) {
            a  = g[(size_t)n0 * (SH * SD) + e];
            bb = g[(size_t)(n0 + 1) * (SH * SD) + e];
        }
        r[i] = make_float2(a, bb);
    }
}
// store V^T bf16 hi/lo, blocked-atom K-major (atom=8rows x 64cols, 8 atom-rows/col)
__device__ __forceinline__ void sts_vt2(const float2* r, char* smc, int w, int lane) {
    #pragma unroll
    for (int i = 0; i < 16; i++) {
        int e = w * 8 + (i & 7);
        int u = lane ^ (4 * (e & 7));
        int n0 = (i >> 3) * 64 + 2 * u;
        uint32_t hi, lo;
        split_pair(r[i].x, r[i].y, hi, lo);   // lo16 = token n0, hi16 = token n0+1
        int atom = (e >> 3) + ((n0 >> 6) << 3);
        int boff = atom * 1024 + (e & 7) * 128 + (n0 & 63) * 2;
        int sw = boff ^ ((boff >> 3) & 0x70);
        *(uint32_t*)(smc + OFF_VHI + sw) = hi;
        *(uint32_t*)(smc + OFF_VLO + sw) = lo;
    }
}

__device__ __forceinline__ void issue_qk(uint32_t smb, uint32_t tS) {
    uint64_t aQh = desc_k(smb + OFF_QHI), aQl = desc_k(smb + OFF_QLO);
    uint64_t bKh = desc_k(smb + OFF_KHI), bKl = desc_k(smb + OFF_KLO);
    uint64_t as[3] = {aQh, aQh, aQl};
    uint64_t bs[3] = {bKh, bKl, bKh};
    uint32_t en = 0;
    #pragma unroll
    for (int tt = 0; tt < 3; tt++)
        #pragma unroll
        for (int k = 0; k < 4; k++) { mma_ss(tS, as[tt] + 2 * k, bs[tt] + 2 * k, IDESC_QK, en); en = 1; }
    COMMIT(smb + OFF_MBQ);
}
__device__ __forceinline__ void issue_pv(uint32_t smb, uint32_t tO, uint32_t en0) {
    uint64_t aPh = desc_k(smb + OFF_PHI), aPl = desc_k(smb + OFF_PLO);
    uint64_t bVh = desc_k(smb + OFF_VHI), bVl = desc_k(smb + OFF_VLO);
    uint64_t as[3] = {aPh, aPh, aPl};
    uint64_t bs[3] = {bVh, bVl, bVh};
    uint32_t en = en0;
    #pragma unroll
    for (int tt = 0; tt < 3; tt++)
        #pragma unroll
        for (int k = 0; k < 8; k++) {
            mma_ss(tO, as[tt] + (k >> 2) * 1024 + (k & 3) * 2,
                       bs[tt] + (k >> 2) * 512  + (k & 3) * 2, IDESC_PV, en);
            en = 1;
        }
    COMMIT(smb + OFF_MBP);
}
#endif  // HAS_TC

__global__ void __launch_bounds__(256, 1)
wk_tc(const float* __restrict__ Q, const float* __restrict__ K,
      const float* __restrict__ V, float* __restrict__ Out, float* __restrict__ Attn)
{
#if HAS_TC
    extern __shared__ char smc[];
    const uint32_t smb = smem_u32(smc);
    const int tid = threadIdx.x;
    const int w = tid >> 5, lane = tid & 31;
    const int sp = w & 3, ch = w >> 2;
    const int m = sp * 32 + lane;

    const int blk = blockIdx.x;
    const int mh = blk & 1, h = (blk >> 1) & 7, c = (blk >> 4) & 31, b = blk >> 9;
    const int q0 = c * 256 + mh * 128;

    if (w == 0) {
        asm volatile("tcgen05.alloc.cta_group::1.sync.aligned.shared::cta.b32 [%0], %1;"
                     :: "r"(smb), "r"(512) : "memory");
        asm volatile("tcgen05.relinquish_alloc_permit.cta_group::1.sync.aligned;");
    }
    if (tid == 0) {
        asm volatile("mbarrier.init.shared.b64 [%0], %1;" :: "r"(smb + OFF_MBQ), "r"(1) : "memory");
        asm volatile("mbarrier.init.shared.b64 [%0], %1;" :: "r"(smb + OFF_MBP), "r"(1) : "memory");
    }
    __syncthreads();
    uint32_t tmem;
    asm volatile("ld.shared.b32 %0, [%1];" : "=r"(tmem) : "r"(smb));
    const uint32_t tS0 = tmem, tS1 = tmem + 128, tO = tmem + 256;

    // Q tile resident all kernel
    {
        float4 qr[8];
        ldg8(Q + ((size_t)(b * SS + q0) * SH + h) * SD, true, tid, qr);
        sts_split(qr, smc, OFF_QHI, OFF_QLO, tid);
    }

    auto kvalid = [&](int t) { int ck = c + (t >> 1) - 1; return (ck >= 0) && (ck < SC); };
    auto kvoff = [&](int t) -> size_t {
        int ck = c + (t >> 1) - 1;
        return ((size_t)(b * SS + ck * 256 + (t & 1) * 128) * SH + h) * SD;
    };

    int phQ = 0, phP = 0;
    float rsum = 0.f;
    float4 kreg[8];
    float2 vreg[16];

    // ================= pass A: rowsums =================
    ldg8(K + kvoff(0), kvalid(0), tid, kreg);
    sts_split(kreg, smc, OFF_KHI, OFF_KLO, tid);
    FENCE_ASYNC();
    __syncthreads();
    if (w == 0 && elect1()) { TM_FENCE_A(); issue_qk(smb, tS0); }
    ldg8(K + kvoff(1), kvalid(1), tid, kreg);

    for (int t = 0; t < 6; t++) {
        MBAR_WAIT(smb + OFF_MBQ, phQ & 1); phQ++;     // QK_t done
        TM_FENCE_A();
        if (t < 5) {
            sts_split(kreg, smc, OFF_KHI, OFF_KLO, tid);   // K_{t+1} (K buf free)
            FENCE_ASYNC();
        }
        __syncthreads();
        if (t < 5 && w == 0 && elect1()) { TM_FENCE_A(); issue_qk(smb, ((t + 1) & 1) ? tS1 : tS0); }
        if (t < 4) ldg8(K + kvoff(t + 2), kvalid(t + 2), tid, kreg);

        const uint32_t tS = (t & 1) ? tS1 : tS0;
        #pragma unroll
        for (int g = 0; g < 2; g++) {
            uint32_t r[32];
            LDTM_X32(r, tS + ch * 64 + g * 32);
            TM_WAIT_LD();
            #pragma unroll
            for (int q = 0; q < 32; q++) rsum += __expf(__uint_as_float(r[q]));
        }
        TM_FENCE_B();
    }

    // rowsum combine -> inv
    *(float*)(smc + OFF_RS + (ch * 128 + m) * 4) = rsum;
    __syncthreads();
    if (tid < 128) {
        float s = *(float*)(smc + OFF_RS + tid * 4) + *(float*)(smc + OFF_RS + (128 + tid) * 4);
        *(float*)(smc + OFF_INV + tid * 4) = 1.0f / s;
    }
    __syncthreads();
    const float inv = *(float*)(smc + OFF_INV + m * 4);
    char* stg = smc + OFF_STG + ch * STG_WG;

    // ================= pass B: attn + PV =================
    ldg8(K + kvoff(0), kvalid(0), tid, kreg);
    sts_split(kreg, smc, OFF_KHI, OFF_KLO, tid);
    FENCE_ASYNC();
    __syncthreads();
    if (w == 0 && elect1()) { TM_FENCE_A(); issue_qk(smb, tS0); }
    ldg_vt(V + kvoff(0), kvalid(0), w, lane, vreg);

    for (int t = 0; t < 6; t++) {
        if (t > 0) { MBAR_WAIT(smb + OFF_MBP, phP & 1); phP++; TM_FENCE_A(); }  // PV_{t-1}
        sts_vt2(vreg, smc, w, lane);                       // V_t (V buf free)
        if (t < 5) ldg8(K + kvoff(t + 1), kvalid(t + 1), tid, kreg);

        MBAR_WAIT(smb + OFF_MBQ, phQ & 1); phQ++;          // QK_t done
        TM_FENCE_A();
        const uint32_t tS = (t & 1) ? tS1 : tS0;
        float* abase = Attn + ((size_t)(b * SS + q0) * SH + h) * SNW + t * 128 + ch * 64;

        #pragma unroll
        for (int g = 0; g < 2; g++) {
            uint32_t r[32];
            LDTM_X32(r, tS + ch * 64 + g * 32);
            TM_WAIT_LD();
            float p[32];
            #pragma unroll
            for (int q = 0; q < 32; q++) p[q] = __expf(__uint_as_float(r[q])) * inv;
            // split normalized P -> smem (blocked-atom layout), stage for coalesced STG
            #pragma unroll
            for (int q = 0; q < 8; q++) {
                int col = ch * 64 + g * 32 + q * 4;
                uint32_t h0, l0, h1, l1;
                split_pair(p[4*q],   p[4*q+1], h0, l0);
                split_pair(p[4*q+2], p[4*q+3], h1, l1);
                int atom = (m >> 3) + ((col >> 6) << 4);
                int boff = atom * 1024 + (m & 7) * 128 + (col & 63) * 2;
                int sw = boff ^ ((boff >> 3) & 0x70);
                *(uint2*)(smc + OFF_PHI + sw) = make_uint2(h0, h1);
                *(uint2*)(smc + OFF_PLO + sw) = make_uint2(l0, l1);
            }
            #pragma unroll
            for (int q = 0; q < 8; q++)
                *(float4*)(stg + (m * STG_STRIDE + q * 4) * 4) =
                    make_float4(p[4*q], p[4*q+1], p[4*q+2], p[4*q+3]);
            TM_FENCE_B();
            if (g == 0) {
                __syncthreads();
                // attn write g=0 (cols +0..31)
                #pragma unroll
                for (int it = 0; it < 8; it++) {
                    int row = it * 16 + sp * 4 + (lane >> 3);
                    int c4 = (lane & 7) << 2;
                    float4 vv = *(const float4*)(stg + (row * STG_STRIDE + c4) * 4);
                    *(float4*)(abase + (size_t)row * (SH * SNW) + c4) = vv;
                }
                __syncthreads();   // all g0 staging reads done before g1 overwrites
            }
        }
        FENCE_ASYNC();
        __syncthreads();                                   // P smem + V smem complete
        if (w == 0 && elect1()) { TM_FENCE_A(); issue_pv(smb, tO, t > 0); }

        // attn write g=1 (cols +32..63) — overlaps PV_t
        #pragma unroll
        for (int it = 0; it < 8; it++) {
            int row = it * 16 + sp * 4 + (lane >> 3);
            int c4 = (lane & 7) << 2;
            float4 vv = *(const float4*)(stg + (row * STG_STRIDE + c4) * 4);
            *(float4*)(abase + (size_t)row * (SH * SNW) + 32 + c4) = vv;
        }
        if (t < 5) {
            sts_split(kreg, smc, OFF_KHI, OFF_KLO, tid);   // K_{t+1} (QK_t done; PV doesn't read K)
            ldg_vt(V + kvoff(t + 1), kvalid(t + 1), w, lane, vreg);
            FENCE_ASYNC();
            __syncthreads();
            if (w == 0 && elect1()) { TM_FENCE_A(); issue_qk(smb, ((t + 1) & 1) ? tS1 : tS0); }
        }
    }
    MBAR_WAIT(smb + OFF_MBP, phP & 1); phP++;              // PV_5
    TM_FENCE_A();

    {   // O epilogue (already normalized)
        uint32_t r[32];
        LDTM_X32(r, tO + ch * 32);
        TM_WAIT_LD();
        TM_FENCE_B();
        float* orow = Out + ((size_t)(b * SS + q0 + m) * SH + h) * SD + ch * 32;
        #pragma unroll
        for (int q = 0; q < 8; q++)
            *(float4*)(orow + q * 4) = make_float4(
                __uint_as_float(r[4*q]),   __uint_as_float(r[4*q+1]),
                __uint_as_float(r[4*q+2]), __uint_as_float(r[4*q+3]));
    }
    __syncthreads();
    if (tid == 0) {
        asm volatile("mbarrier.inval.shared.b64 [%0];" :: "r"(smb + OFF_MBQ) : "memory");
        asm volatile("mbarrier.inval.shared.b64 [%0];" :: "r"(smb + OFF_MBP) : "memory");
    }
    __syncthreads();
    if (w == 0)
        asm volatile("tcgen05.dealloc.cta_group::1.sync.aligned.b32 %0, %1;" :: "r"(tmem), "r"(512));
#endif  // HAS_TC
}

// ================= SIMT fallback =================
#define MT 32
#define NTILE 128
#define KSTR 68
#define SMEM_FLOATS (MT*SNW + MT*KSTR + NTILE*KSTR + MT)

__global__ void __launch_bounds__(256, 1)
wk_simt(const float* __restrict__ Q, const float* __restrict__ K,
        const float* __restrict__ V, float* __restrict__ Out, float* __restrict__ Attn)
{
    extern __shared__ float sm[];
    float* sP = sm;
    float* sQ = sP + MT * SNW;
    float* sKV = sQ + MT * KSTR;
    float* sSum = sKV + NTILE * KSTR;
    const int tid = threadIdx.x, tx = tid & 31, ty = tid >> 5;
    const int blk = blockIdx.x;
    const int mblk = blk & 7, h = (blk >> 3) & 7, c = (blk >> 6) & 31, b = blk >> 11;
    const int q0 = c * 256 + mblk * MT;
    if (tid < MT) sSum[tid] = 0.0f;
    for (int i = tid; i < MT * 16; i += 256) {
        int mm = i >> 4, d4 = (i & 15) << 2;
        *(float4*)&sQ[mm * KSTR + d4] = *(const float4*)&Q[((((size_t)b*SS)+q0+mm)*SH+h)*SD + d4];
    }
    for (int t = 0; t < 6; t++) {
        int ck = c + (t >> 1) - 1, koff = (t & 1) * NTILE;
        bool valid = (ck >= 0) && (ck < SC);
        for (int i = tid; i < NTILE * 16; i += 256) {
            int n = i >> 4, d4 = (i & 15) << 2;
            float4 kv = make_float4(0.f,0.f,0.f,0.f);
            if (valid) kv = *(const float4*)&K[((((size_t)b*SS)+ck*256+koff+n)*SH+h)*SD + d4];
            *(float4*)&sKV[n * KSTR + d4] = kv;
        }
        __syncthreads();
        float acc[4][4];
        #pragma unroll
        for (int mi = 0; mi < 4; mi++) { acc[mi][0]=acc[mi][1]=acc[mi][2]=acc[mi][3]=0.f; }
        #pragma unroll
        for (int kk = 0; kk < SD; kk += 4) {
            float4 qv[4], kv[4];
            #pragma unroll
            for (int mi = 0; mi < 4; mi++) qv[mi] = *(const float4*)&sQ[(ty*4+mi)*KSTR + kk];
            #pragma unroll
            for (int ni = 0; ni < 4; ni++) kv[ni] = *(const float4*)&sKV[(tx+32*ni)*KSTR + kk];
            #pragma unroll
            for (int mi = 0; mi < 4; mi++)
                #pragma unroll
                for (int ni = 0; ni < 4; ni++)
                    acc[mi][ni] += qv[mi].x*kv[ni].x + qv[mi].y*kv[ni].y
                                 + qv[mi].z*kv[ni].z + qv[mi].w*kv[ni].w;
        }
        #pragma unroll
        for (int mi = 0; mi < 4; mi++) {
            int mm = ty*4+mi;
            float rs = 0.f;
            #pragma unroll
            for (int ni = 0; ni < 4; ni++) {
                float p = __expf(acc[mi][ni]);
                sP[mm*SNW + t*NTILE + tx + 32*ni] = p;
                rs += p;
            }
            #pragma unroll
            for (int off = 16; off > 0; off >>= 1) rs += __shfl_xor_sync(0xffffffffu, rs, off);
            if (tx == 0) sSum[mm] += rs;
        }
        __syncthreads();
    }
    if (tid < MT) sSum[tid] = 1.0f / sSum[tid];
    __syncthreads();
    #pragma unroll 4
    for (int i = tid; i < MT * 192; i += 256) {
        int mm = i / 192, j4 = (i - mm*192) << 2;
        float4 p = *(const float4*)&sP[mm*SNW + j4];
        float iv = sSum[mm];
        p.x*=iv; p.y*=iv; p.z*=iv; p.w*=iv;
        *(float4*)&Attn[((((size_t)b*SS)+q0+mm)*SH+h)*SNW + j4] = p;
    }
    float acco[4][2];
    #pragma unroll
    for (int mi = 0; mi < 4; mi++) { acco[mi][0]=0.f; acco[mi][1]=0.f; }
    for (int t = 0; t < 6; t++) {
        int ck = c + (t >> 1) - 1, koff = (t & 1) * NTILE;
        bool valid = (ck >= 0) && (ck < SC);
        __syncthreads();
        for (int i = tid; i < NTILE * 16; i += 256) {
            int n = i >> 4, d4 = (i & 15) << 2;
            float4 vv = make_float4(0.f,0.f,0.f,0.f);
            if (valid) vv = *(const float4*)&V[((((size_t)b*SS)+ck*256+koff+n)*SH+h)*SD + d4];
            *(float4*)&sKV[n * KSTR + d4] = vv;
        }
        __syncthreads();
        #pragma unroll 8
        for (int kk = 0; kk < NTILE; kk += 4) {
            float4 pv[4];
            #pragma unroll
            for (int mi = 0; mi < 4; mi++) pv[mi] = *(const float4*)&sP[(ty*4+mi)*SNW + t*NTILE + kk];
            #pragma unroll
            for (int u = 0; u < 4; u++) {
                float va0 = sKV[(kk+u)*KSTR + tx], va1 = sKV[(kk+u)*KSTR + tx + 32];
                #pragma unroll
                for (int mi = 0; mi < 4; mi++) {
                    float pm = (u==0)?pv[mi].x:(u==1)?pv[mi].y:(u==2)?pv[mi].z:pv[mi].w;
                    acco[mi][0] += pm*va0;
                    acco[mi][1] += pm*va1;
                }
            }
        }
    }
    #pragma unroll
    for (int mi = 0; mi < 4; mi++) {
        int mm = ty*4+mi;
        float iv = sSum[mm];
        float* op = &Out[((((size_t)b*SS)+q0+mm)*SH+h)*SD];
        op[tx] = acco[mi][0]*iv;
        op[tx+32] = acco[mi][1]*iv;
    }
}

extern "C" void kernel_launch(void* const* d_in, const int* in_sizes, int n_in,
                              void* d_out, int out_size)
{
    const float* q = (const float*)d_in[0];
    const float* k = (const float*)d_in[1];
    const float* v = (const float*)d_in[2];
    float* out  = (float*)d_out;
    float* attn = out + (size_t)SB * SS * SH * SD;   // [output | attention]

    cudaFuncAttributes fa{};
    cudaFuncGetAttributes(&fa, wk_tc);
    if (fa.numRegs >= 40) {
        cudaFuncSetAttribute(wk_tc, cudaFuncAttributeMaxDynamicSharedMemorySize, SMEM_TC);
        wk_tc<<<SB * SC * SH * 2, 256, SMEM_TC>>>(q, k, v, out, attn);
    } else {
        const int smem = SMEM_FLOATS * sizeof(float);
        cudaFuncSetAttribute(wk_simt, cudaFuncAttributeMaxDynamicSharedMemorySize, smem);
        wk_simt<<<SB * SC * SH * 8, 256, smem>>>(q, k, v, out, attn);
    }
}

// round 10
// speedup vs baseline: 1.1799x; 1.1799x over previous
#include <cuda_runtime.h>
#include <cuda_bf16.h>
#include <cstdint>

#define SB 2
#define SS 8192
#define SH 8
#define SD 64
#define SC 32
#define SNW 768

#if defined(__CUDA_ARCH_FEAT_SM103_ALL) || defined(__CUDA_ARCH_FEAT_SM100_ALL) || \
    defined(__CUDA_ARCH_FEAT_SM101_ALL) || defined(__CUDA_ARCH_FEAT_SM110_ALL)
#define HAS_TC 1
#else
#define HAS_TC 0
#endif

// smem layout (bytes)
#define OFF_MBQ   8
#define OFF_MBP   16
#define OFF_RS    32
#define OFF_INV   1056
#define OFF_QHI   2048
#define OFF_QLO   18432
#define OFF_KHI   34816
#define OFF_KLO   51200
#define OFF_VHI   67584
#define OFF_VLO   83968
#define OFF_PHI   100352
#define OFF_PLO   133120
#define OFF_STG   165888
#define STG_STRIDE 36            /* floats; 144B row pitch = 16B-aligned */
#define STG_WG    18432
#define SMEM_TC   202752

#define IDESC_QK 0x08200490u   /* M=128 N=128 */
#define IDESC_PV 0x08100490u   /* M=128 N=64  */

#if HAS_TC
__device__ __forceinline__ uint32_t smem_u32(const void* p) {
    uint32_t a;
    asm("{ .reg .u64 t; cvta.to.shared.u64 t, %1; cvt.u32.u64 %0, t; }" : "=r"(a) : "l"(p));
    return a;
}
__device__ __forceinline__ uint32_t elect1() {
    uint32_t p;
    asm volatile("{ .reg .pred p; elect.sync _|p, 0xFFFFFFFF; selp.b32 %0, 1, 0, p; }" : "=r"(p));
    return p;
}
__device__ __forceinline__ uint64_t desc_k(uint32_t a) {   // K-major SW128: LBO=1, SBO=64
    return (2ull << 61) | (1ull << 46) | (64ull << 32) | (1ull << 16) | ((a >> 4) & 0x3FFF);
}
__device__ __forceinline__ void mma_ss(uint32_t d, uint64_t a, uint64_t b, uint32_t id, uint32_t en) {
    asm volatile(
        "{\n\t.reg .pred p;\n\tsetp.ne.u32 p, %4, 0;\n\t"
        "tcgen05.mma.cta_group::1.kind::f16 [%0], %1, %2, %3, {%5, %5, %5, %5}, p;\n\t}"
        :: "r"(d), "l"(a), "l"(b), "r"(id), "r"(en), "r"(0u) : "memory");
}
#define TM_FENCE_A() asm volatile("tcgen05.fence::after_thread_sync;" ::: "memory")
#define TM_FENCE_B() asm volatile("tcgen05.fence::before_thread_sync;" ::: "memory")
#define TM_WAIT_LD() asm volatile("tcgen05.wait::ld.sync.aligned;" ::: "memory")
#define FENCE_ASYNC() asm volatile("fence.proxy.async.shared::cta;" ::: "memory")
#define COMMIT(mb) asm volatile("tcgen05.commit.cta_group::1.mbarrier::arrive::one.shared::cluster.b64 [%0];" :: "r"(mb) : "memory")

#define MBAR_WAIT(mb, pa) do {                                                            \
    asm volatile("{\n\t.reg .pred P1;\n\t"                                                \
        "WL%=:\n\t"                                                                       \
        "mbarrier.try_wait.parity.acquire.cta.shared::cta.b64 P1, [%0], %1, 0x989680;\n\t"\
        "@P1 bra.uni WD%=;\n\t"                                                           \
        "bra.uni WL%=;\n\t"                                                               \
        "WD%=:\n\t}" :: "r"(mb), "r"(pa) : "memory");                                     \
} while (0)

#define LDTM_X32(r, a)                                                                    \
    asm volatile("tcgen05.ld.sync.aligned.32x32b.x32.b32 "                                \
        "{%0, %1, %2, %3, %4, %5, %6, %7, %8, %9, %10, %11, %12, %13, %14, %15, "         \
        " %16, %17, %18, %19, %20, %21, %22, %23, %24, %25, %26, %27, %28, %29, %30, %31}, [%32];" \
        : "=r"((r)[0]),  "=r"((r)[1]),  "=r"((r)[2]),  "=r"((r)[3]),                      \
          "=r"((r)[4]),  "=r"((r)[5]),  "=r"((r)[6]),  "=r"((r)[7]),                      \
          "=r"((r)[8]),  "=r"((r)[9]),  "=r"((r)[10]), "=r"((r)[11]),                     \
          "=r"((r)[12]), "=r"((r)[13]), "=r"((r)[14]), "=r"((r)[15]),                     \
          "=r"((r)[16]), "=r"((r)[17]), "=r"((r)[18]), "=r"((r)[19]),                     \
          "=r"((r)[20]), "=r"((r)[21]), "=r"((r)[22]), "=r"((r)[23]),                     \
          "=r"((r)[24]), "=r"((r)[25]), "=r"((r)[26]), "=r"((r)[27]),                     \
          "=r"((r)[28]), "=r"((r)[29]), "=r"((r)[30]), "=r"((r)[31])                      \
        : "r"(a))

__device__ __forceinline__ void split_pair(float a, float b, uint32_t& hi, uint32_t& lo) {
    uint32_t h;
    asm("cvt.rn.bf16x2.f32 %0, %1, %2;" : "=r"(h) : "f"(b), "f"(a));  // lo16=a, hi16=b
    float fa = __uint_as_float(h << 16);
    float fb = __uint_as_float(h & 0xffff0000u);
    uint32_t l;
    asm("cvt.rn.bf16x2.f32 %0, %1, %2;" : "=r"(l) : "f"(b - fb), "f"(a - fa));
    hi = h; lo = l;
}

// prefetch 128x64 fp32 tile into 8 float4 regs (coalesced)
__device__ __forceinline__ void ldg8(const float* __restrict__ g, bool valid, int tid, float4* r) {
    #pragma unroll
    for (int it = 0; it < 8; it++) {
        int i = it * 256 + tid;
        int n = i >> 4, e4 = (i & 15) << 2;
        r[it] = valid ? *(const float4*)(g + (size_t)n * (SH * SD) + e4)
                      : make_float4(0.f, 0.f, 0.f, 0.f);
    }
}
// regs -> bf16 hi/lo, K-major SW128 128B rows (Q and K tiles)
__device__ __forceinline__ void sts_split(const float4* r, char* smc, int offhi, int offlo, int tid) {
    #pragma unroll
    for (int it = 0; it < 8; it++) {
        int i = it * 256 + tid;
        int n = i >> 4, e4 = (i & 15) << 2;
        uint32_t h0, l0, h1, l1;
        split_pair(r[it].x, r[it].y, h0, l0);
        split_pair(r[it].z, r[it].w, h1, l1);
        int boff = n * 128 + e4 * 2;
        int sw = boff ^ ((boff >> 3) & 0x70);
        *(uint2*)(smc + offhi + sw) = make_uint2(h0, h1);
        *(uint2*)(smc + offlo + sw) = make_uint2(l0, l1);
    }
}
// V regs [tok][dim] -> V^T bf16 hi/lo, blocked-atom K-major (atom=8x64, 8 atom-rows).
// Per-lane dim rotation j_eff=(j+((tid&15)>>1))&3 spreads the 8 same-bank lanes
// over 4 dim-rows -> 8-way conflict becomes 2-way.
__device__ __forceinline__ void sts_vt(const float4* r, char* smc, int tid) {
    const int rot = (tid & 15) >> 1;
    #pragma unroll
    for (int it = 0; it < 8; it++) {
        int i = it * 256 + tid;
        int n = i >> 4, e4 = (i & 15) << 2;
        float vals[4] = {r[it].x, r[it].y, r[it].z, r[it].w};
        #pragma unroll
        for (int j = 0; j < 4; j++) {
            int jr = (j + rot) & 3;
            int e = e4 + jr;
            __nv_bfloat16 h = __float2bfloat16_rn(vals[jr]);
            __nv_bfloat16 l = __float2bfloat16_rn(vals[jr] - __bfloat162float(h));
            int atom = (e >> 3) + ((n >> 6) << 3);
            int boff = atom * 1024 + (e & 7) * 128 + (n & 63) * 2;
            int sw = boff ^ ((boff >> 3) & 0x70);
            *(unsigned short*)(smc + OFF_VHI + sw) = __bfloat16_as_ushort(h);
            *(unsigned short*)(smc + OFF_VLO + sw) = __bfloat16_as_ushort(l);
        }
    }
}

__device__ __forceinline__ void issue_qk(uint32_t smb, uint32_t tS) {
    uint64_t aQh = desc_k(smb + OFF_QHI), aQl = desc_k(smb + OFF_QLO);
    uint64_t bKh = desc_k(smb + OFF_KHI), bKl = desc_k(smb + OFF_KLO);
    uint64_t as[3] = {aQh, aQh, aQl};
    uint64_t bs[3] = {bKh, bKl, bKh};
    uint32_t en = 0;
    #pragma unroll
    for (int tt = 0; tt < 3; tt++)
        #pragma unroll
        for (int k = 0; k < 4; k++) { mma_ss(tS, as[tt] + 2 * k, bs[tt] + 2 * k, IDESC_QK, en); en = 1; }
    COMMIT(smb + OFF_MBQ);
}
__device__ __forceinline__ void issue_pv(uint32_t smb, uint32_t tO, uint32_t en0) {
    uint64_t aPh = desc_k(smb + OFF_PHI), aPl = desc_k(smb + OFF_PLO);
    uint64_t bVh = desc_k(smb + OFF_VHI), bVl = desc_k(smb + OFF_VLO);
    uint64_t as[3] = {aPh, aPh, aPl};
    uint64_t bs[3] = {bVh, bVl, bVh};
    uint32_t en = en0;
    #pragma unroll
    for (int tt = 0; tt < 3; tt++)
        #pragma unroll
        for (int k = 0; k < 8; k++) {
            mma_ss(tO, as[tt] + (k >> 2) * 1024 + (k & 3) * 2,
                       bs[tt] + (k >> 2) * 512  + (k & 3) * 2, IDESC_PV, en);
            en = 1;
        }
    COMMIT(smb + OFF_MBP);
}
#endif  // HAS_TC

__global__ void __launch_bounds__(256, 1)
wk_tc(const float* __restrict__ Q, const float* __restrict__ K,
      const float* __restrict__ V, float* __restrict__ Out, float* __restrict__ Attn)
{
#if HAS_TC
    extern __shared__ char smc[];
    const uint32_t smb = smem_u32(smc);
    const int tid = threadIdx.x;
    const int w = tid >> 5, lane = tid & 31;
    const int sp = w & 3, ch = w >> 2;
    const int m = sp * 32 + lane;

    const int blk = blockIdx.x;
    const int mh = blk & 1, h = (blk >> 1) & 7, c = (blk >> 4) & 31, b = blk >> 9;
    const int q0 = c * 256 + mh * 128;

    if (w == 0) {
        asm volatile("tcgen05.alloc.cta_group::1.sync.aligned.shared::cta.b32 [%0], %1;"
                     :: "r"(smb), "r"(512) : "memory");
        asm volatile("tcgen05.relinquish_alloc_permit.cta_group::1.sync.aligned;");
    }
    if (tid == 0) {
        asm volatile("mbarrier.init.shared.b64 [%0], %1;" :: "r"(smb + OFF_MBQ), "r"(1) : "memory");
        asm volatile("mbarrier.init.shared.b64 [%0], %1;" :: "r"(smb + OFF_MBP), "r"(1) : "memory");
    }
    __syncthreads();
    uint32_t tmem;
    asm volatile("ld.shared.b32 %0, [%1];" : "=r"(tmem) : "r"(smb));
    const uint32_t tS0 = tmem, tS1 = tmem + 128, tO = tmem + 256;

    // Q tile resident all kernel
    {
        float4 qr[8];
        ldg8(Q + ((size_t)(b * SS + q0) * SH + h) * SD, true, tid, qr);
        sts_split(qr, smc, OFF_QHI, OFF_QLO, tid);
    }

    auto kvalid = [&](int t) { int ck = c + (t >> 1) - 1; return (ck >= 0) && (ck < SC); };
    auto kvoff = [&](int t) -> size_t {
        int ck = c + (t >> 1) - 1;
        return ((size_t)(b * SS + ck * 256 + (t & 1) * 128) * SH + h) * SD;
    };

    int phQ = 0, phP = 0;
    float rsum = 0.f;
    float4 kreg[8], vreg[8];

    // ================= pass A: rowsums =================
    ldg8(K + kvoff(0), kvalid(0), tid, kreg);
    sts_split(kreg, smc, OFF_KHI, OFF_KLO, tid);
    FENCE_ASYNC();
    __syncthreads();
    if (w == 0 && elect1()) { TM_FENCE_A(); issue_qk(smb, tS0); }
    ldg8(K + kvoff(1), kvalid(1), tid, kreg);

    for (int t = 0; t < 6; t++) {
        MBAR_WAIT(smb + OFF_MBQ, phQ & 1); phQ++;     // QK_t done
        TM_FENCE_A();
        if (t < 5) {
            sts_split(kreg, smc, OFF_KHI, OFF_KLO, tid);   // K_{t+1} (K buf free)
            FENCE_ASYNC();
        }
        __syncthreads();
        if (t < 5 && w == 0 && elect1()) { TM_FENCE_A(); issue_qk(smb, ((t + 1) & 1) ? tS1 : tS0); }
        if (t < 4) ldg8(K + kvoff(t + 2), kvalid(t + 2), tid, kreg);

        const uint32_t tS = (t & 1) ? tS1 : tS0;
        #pragma unroll
        for (int g = 0; g < 2; g++) {
            uint32_t r[32];
            LDTM_X32(r, tS + ch * 64 + g * 32);
            TM_WAIT_LD();
            #pragma unroll
            for (int q = 0; q < 32; q++) rsum += __expf(__uint_as_float(r[q]));
        }
        TM_FENCE_B();
    }

    // rowsum combine -> inv
    *(float*)(smc + OFF_RS + (ch * 128 + m) * 4) = rsum;
    __syncthreads();
    if (tid < 128) {
        float s = *(float*)(smc + OFF_RS + tid * 4) + *(float*)(smc + OFF_RS + (128 + tid) * 4);
        *(float*)(smc + OFF_INV + tid * 4) = 1.0f / s;
    }
    __syncthreads();
    const float inv = *(float*)(smc + OFF_INV + m * 4);
    char* stg = smc + OFF_STG + ch * STG_WG;

    // ================= pass B: attn + PV =================
    ldg8(K + kvoff(0), kvalid(0), tid, kreg);
    sts_split(kreg, smc, OFF_KHI, OFF_KLO, tid);
    FENCE_ASYNC();
    __syncthreads();
    if (w == 0 && elect1()) { TM_FENCE_A(); issue_qk(smb, tS0); }
    ldg8(V + kvoff(0), kvalid(0), tid, vreg);

    for (int t = 0; t < 6; t++) {
        if (t > 0) { MBAR_WAIT(smb + OFF_MBP, phP & 1); phP++; TM_FENCE_A(); }  // PV_{t-1}
        sts_vt(vreg, smc, tid);                            // V_t (V buf free)
        if (t < 5) ldg8(K + kvoff(t + 1), kvalid(t + 1), tid, kreg);

        MBAR_WAIT(smb + OFF_MBQ, phQ & 1); phQ++;          // QK_t done
        TM_FENCE_A();
        const uint32_t tS = (t & 1) ? tS1 : tS0;
        float* abase = Attn + ((size_t)(b * SS + q0) * SH + h) * SNW + t * 128 + ch * 64;

        #pragma unroll
        for (int g = 0; g < 2; g++) {
            uint32_t r[32];
            LDTM_X32(r, tS + ch * 64 + g * 32);
            TM_WAIT_LD();
            float p[32];
            #pragma unroll
            for (int q = 0; q < 32; q++) p[q] = __expf(__uint_as_float(r[q])) * inv;
            // split normalized P -> smem (blocked-atom layout); per-lane column-group
            // rotation qr=(q+(lane>>3))&7 makes the 4 same-(r,t) lanes hit distinct
            // token groups -> conflict-free
            #pragma unroll
            for (int q = 0; q < 8; q++) {
                int qr = (q + (lane >> 3)) & 7;
                int col = ch * 64 + g * 32 + qr * 4;
                uint32_t h0, l0, h1, l1;
                split_pair(p[4*qr],   p[4*qr+1], h0, l0);
                split_pair(p[4*qr+2], p[4*qr+3], h1, l1);
                int atom = (m >> 3) + ((col >> 6) << 4);
                int boff = atom * 1024 + (m & 7) * 128 + (col & 63) * 2;
                int sw = boff ^ ((boff >> 3) & 0x70);
                *(uint2*)(smc + OFF_PHI + sw) = make_uint2(h0, h1);
                *(uint2*)(smc + OFF_PLO + sw) = make_uint2(l0, l1);
            }
            #pragma unroll
            for (int q = 0; q < 8; q++)
                *(float4*)(stg + (m * STG_STRIDE + q * 4) * 4) =
                    make_float4(p[4*q], p[4*q+1], p[4*q+2], p[4*q+3]);
            TM_FENCE_B();
            if (g == 0) {
                __syncthreads();
                // attn write g=0 (cols +0..31)
                #pragma unroll
                for (int it = 0; it < 8; it++) {
                    int row = it * 16 + sp * 4 + (lane >> 3);
                    int c4 = (lane & 7) << 2;
                    float4 vv = *(const float4*)(stg + (row * STG_STRIDE + c4) * 4);
                    *(float4*)(abase + (size_t)row * (SH * SNW) + c4) = vv;
                }
                __syncthreads();   // all g0 staging reads done before g1 overwrites
            }
        }
        FENCE_ASYNC();
        __syncthreads();                                   // P smem + V smem complete
        if (w == 0 && elect1()) { TM_FENCE_A(); issue_pv(smb, tO, t > 0); }

        // attn write g=1 (cols +32..63) — overlaps PV_t
        #pragma unroll
        for (int it = 0; it < 8; it++) {
            int row = it * 16 + sp * 4 + (lane >> 3);
            int c4 = (lane & 7) << 2;
            float4 vv = *(const float4*)(stg + (row * STG_STRIDE + c4) * 4);
            *(float4*)(abase + (size_t)row * (SH * SNW) + 32 + c4) = vv;
        }
        if (t < 5) {
            sts_split(kreg, smc, OFF_KHI, OFF_KLO, tid);   // K_{t+1} (QK_t done; PV doesn't read K)
            ldg8(V + kvoff(t + 1), kvalid(t + 1), tid, vreg);
            FENCE_ASYNC();
            __syncthreads();
            if (w == 0 && elect1()) { TM_FENCE_A(); issue_qk(smb, ((t + 1) & 1) ? tS1 : tS0); }
        }
    }
    MBAR_WAIT(smb + OFF_MBP, phP & 1); phP++;              // PV_5
    TM_FENCE_A();

    {   // O epilogue (already normalized)
        uint32_t r[32];
        LDTM_X32(r, tO + ch * 32);
        TM_WAIT_LD();
        TM_FENCE_B();
        float* orow = Out + ((size_t)(b * SS + q0 + m) * SH + h) * SD + ch * 32;
        #pragma unroll
        for (int q = 0; q < 8; q++)
            *(float4*)(orow + q * 4) = make_float4(
                __uint_as_float(r[4*q]),   __uint_as_float(r[4*q+1]),
                __uint_as_float(r[4*q+2]), __uint_as_float(r[4*q+3]));
    }
    __syncthreads();
    if (tid == 0) {
        asm volatile("mbarrier.inval.shared.b64 [%0];" :: "r"(smb + OFF_MBQ) : "memory");
        asm volatile("mbarrier.inval.shared.b64 [%0];" :: "r"(smb + OFF_MBP) : "memory");
    }
    __syncthreads();
    if (w == 0)
        asm volatile("tcgen05.dealloc.cta_group::1.sync.aligned.b32 %0, %1;" :: "r"(tmem), "r"(512));
#endif  // HAS_TC
}

// ================= SIMT fallback =================
#define MT 32
#define NTILE 128
#define KSTR 68
#define SMEM_FLOATS (MT*SNW + MT*KSTR + NTILE*KSTR + MT)

__global__ void __launch_bounds__(256, 1)
wk_simt(const float* __restrict__ Q, const float* __restrict__ K,
        const float* __restrict__ V, float* __restrict__ Out, float* __restrict__ Attn)
{
    extern __shared__ float sm[];
    float* sP = sm;
    float* sQ = sP + MT * SNW;
    float* sKV = sQ + MT * KSTR;
    float* sSum = sKV + NTILE * KSTR;
    const int tid = threadIdx.x, tx = tid & 31, ty = tid >> 5;
    const int blk = blockIdx.x;
    const int mblk = blk & 7, h = (blk >> 3) & 7, c = (blk >> 6) & 31, b = blk >> 11;
    const int q0 = c * 256 + mblk * MT;
    if (tid < MT) sSum[tid] = 0.0f;
    for (int i = tid; i < MT * 16; i += 256) {
        int mm = i >> 4, d4 = (i & 15) << 2;
        *(float4*)&sQ[mm * KSTR + d4] = *(const float4*)&Q[((((size_t)b*SS)+q0+mm)*SH+h)*SD + d4];
    }
    for (int t = 0; t < 6; t++) {
        int ck = c + (t >> 1) - 1, koff = (t & 1) * NTILE;
        bool valid = (ck >= 0) && (ck < SC);
        for (int i = tid; i < NTILE * 16; i += 256) {
            int n = i >> 4, d4 = (i & 15) << 2;
            float4 kv = make_float4(0.f,0.f,0.f,0.f);
            if (valid) kv = *(const float4*)&K[((((size_t)b*SS)+ck*256+koff+n)*SH+h)*SD + d4];
            *(float4*)&sKV[n * KSTR + d4] = kv;
        }
        __syncthreads();
        float acc[4][4];
        #pragma unroll
        for (int mi = 0; mi < 4; mi++) { acc[mi][0]=acc[mi][1]=acc[mi][2]=acc[mi][3]=0.f; }
        #pragma unroll
        for (int kk = 0; kk < SD; kk += 4) {
            float4 qv[4], kv[4];
            #pragma unroll
            for (int mi = 0; mi < 4; mi++) qv[mi] = *(const float4*)&sQ[(ty*4+mi)*KSTR + kk];
            #pragma unroll
            for (int ni = 0; ni < 4; ni++) kv[ni] = *(const float4*)&sKV[(tx+32*ni)*KSTR + kk];
            #pragma unroll
            for (int mi = 0; mi < 4; mi++)
                #pragma unroll
                for (int ni = 0; ni < 4; ni++)
                    acc[mi][ni] += qv[mi].x*kv[ni].x + qv[mi].y*kv[ni].y
                                 + qv[mi].z*kv[ni].z + qv[mi].w*kv[ni].w;
        }
        #pragma unroll
        for (int mi = 0; mi < 4; mi++) {
            int mm = ty*4+mi;
            float rs = 0.f;
            #pragma unroll
            for (int ni = 0; ni < 4; ni++) {
                float p = __expf(acc[mi][ni]);
                sP[mm*SNW + t*NTILE + tx + 32*ni] = p;
                rs += p;
            }
            #pragma unroll
            for (int off = 16; off > 0; off >>= 1) rs += __shfl_xor_sync(0xffffffffu, rs, off);
            if (tx == 0) sSum[mm] += rs;
        }
        __syncthreads();
    }
    if (tid < MT) sSum[tid] = 1.0f / sSum[tid];
    __syncthreads();
    #pragma unroll 4
    for (int i = tid; i < MT * 192; i += 256) {
        int mm = i / 192, j4 = (i - mm*192) << 2;
        float4 p = *(const float4*)&sP[mm*SNW + j4];
        float iv = sSum[mm];
        p.x*=iv; p.y*=iv; p.z*=iv; p.w*=iv;
        *(float4*)&Attn[((((size_t)b*SS)+q0+mm)*SH+h)*SNW + j4] = p;
    }
    float acco[4][2];
    #pragma unroll
    for (int mi = 0; mi < 4; mi++) { acco[mi][0]=0.f; acco[mi][1]=0.f; }
    for (int t = 0; t < 6; t++) {
        int ck = c + (t >> 1) - 1, koff = (t & 1) * NTILE;
        bool valid = (ck >= 0) && (ck < SC);
        __syncthreads();
        for (int i = tid; i < NTILE * 16; i += 256) {
            int n = i >> 4, d4 = (i & 15) << 2;
            float4 vv = make_float4(0.f,0.f,0.f,0.f);
            if (valid) vv = *(const float4*)&V[((((size_t)b*SS)+ck*256+koff+n)*SH+h)*SD + d4];
            *(float4*)&sKV[n * KSTR + d4] = vv;
        }
        __syncthreads();
        #pragma unroll 8
        for (int kk = 0; kk < NTILE; kk += 4) {
            float4 pv[4];
            #pragma unroll
            for (int mi = 0; mi < 4; mi++) pv[mi] = *(const float4*)&sP[(ty*4+mi)*SNW + t*NTILE + kk];
            #pragma unroll
            for (int u = 0; u < 4; u++) {
                float va0 = sKV[(kk+u)*KSTR + tx], va1 = sKV[(kk+u)*KSTR + tx + 32];
                #pragma unroll
                for (int mi = 0; mi < 4; mi++) {
                    float pm = (u==0)?pv[mi].x:(u==1)?pv[mi].y:(u==2)?pv[mi].z:pv[mi].w;
                    acco[mi][0] += pm*va0;
                    acco[mi][1] += pm*va1;
                }
            }
        }
    }
    #pragma unroll
    for (int mi = 0; mi < 4; mi++) {
        int mm = ty*4+mi;
        float iv = sSum[mm];
        float* op = &Out[((((size_t)b*SS)+q0+mm)*SH+h)*SD];
        op[tx] = acco[mi][0]*iv;
        op[tx+32] = acco[mi][1]*iv;
    }
}

extern "C" void kernel_launch(void* const* d_in, const int* in_sizes, int n_in,
                              void* d_out, int out_size)
{
    const float* q = (const float*)d_in[0];
    const float* k = (const float*)d_in[1];
    const float* v = (const float*)d_in[2];
    float* out  = (float*)d_out;
    float* attn = out + (size_t)SB * SS * SH * SD;   // [output | attention]

    cudaFuncAttributes fa{};
    cudaFuncGetAttributes(&fa, wk_tc);
    if (fa.numRegs >= 40) {
        cudaFuncSetAttribute(wk_tc, cudaFuncAttributeMaxDynamicSharedMemorySize, SMEM_TC);
        wk_tc<<<SB * SC * SH * 2, 256, SMEM_TC>>>(q, k, v, out, attn);
    } else {
        const int smem = SMEM_FLOATS * sizeof(float);
        cudaFuncSetAttribute(wk_simt, cudaFuncAttributeMaxDynamicSharedMemorySize, smem);
        wk_simt<<<SB * SC * SH * 8, 256, smem>>>(q, k, v, out, attn);
    }
}

// round 11
// speedup vs baseline: 1.5176x; 1.2862x over previous
#include <cuda_runtime.h>
#include <cuda_bf16.h>
#include <cstdint>

#define SB 2
#define SS 8192
#define SH 8
#define SD 64
#define SC 32
#define SNW 768

#if defined(__CUDA_ARCH_FEAT_SM103_ALL) || defined(__CUDA_ARCH_FEAT_SM100_ALL) || \
    defined(__CUDA_ARCH_FEAT_SM101_ALL) || defined(__CUDA_ARCH_FEAT_SM110_ALL)
#define HAS_TC 1
#else
#define HAS_TC 0
#endif

// smem layout (bytes)
#define OFF_MBQ   8
#define OFF_MBP   16
#define OFF_RS    32
#define OFF_INV   1056
#define OFF_QHI   2048
#define OFF_QLO   18432
#define OFF_KHI   34816
#define OFF_KLO   51200
#define OFF_VHI   67584
#define OFF_PHI   100352
#define OFF_STG   165888
#define STG_STRIDE 36            /* floats; 144B row pitch = 16B-aligned */
#define STG_WG    18432
#define SMEM_TC   202752

#define IDESC_QK 0x08200490u   /* M=128 N=128, bf16 inputs */
#define IDESC_PV 0x08100010u   /* M=128 N=64,  fp16 inputs */

#if HAS_TC
__device__ __forceinline__ uint32_t smem_u32(const void* p) {
    uint32_t a;
    asm("{ .reg .u64 t; cvta.to.shared.u64 t, %1; cvt.u32.u64 %0, t; }" : "=r"(a) : "l"(p));
    return a;
}
__device__ __forceinline__ uint32_t elect1() {
    uint32_t p;
    asm volatile("{ .reg .pred p; elect.sync _|p, 0xFFFFFFFF; selp.b32 %0, 1, 0, p; }" : "=r"(p));
    return p;
}
__device__ __forceinline__ uint64_t desc_k(uint32_t a) {   // K-major SW128: LBO=1, SBO=64
    return (2ull << 61) | (1ull << 46) | (64ull << 32) | (1ull << 16) | ((a >> 4) & 0x3FFF);
}
__device__ __forceinline__ void mma_ss(uint32_t d, uint64_t a, uint64_t b, uint32_t id, uint32_t en) {
    asm volatile(
        "{\n\t.reg .pred p;\n\tsetp.ne.u32 p, %4, 0;\n\t"
        "tcgen05.mma.cta_group::1.kind::f16 [%0], %1, %2, %3, {%5, %5, %5, %5}, p;\n\t}"
        :: "r"(d), "l"(a), "l"(b), "r"(id), "r"(en), "r"(0u) : "memory");
}
#define TM_FENCE_A() asm volatile("tcgen05.fence::after_thread_sync;" ::: "memory")
#define TM_FENCE_B() asm volatile("tcgen05.fence::before_thread_sync;" ::: "memory")
#define TM_WAIT_LD() asm volatile("tcgen05.wait::ld.sync.aligned;" ::: "memory")
#define FENCE_ASYNC() asm volatile("fence.proxy.async.shared::cta;" ::: "memory")
#define COMMIT(mb) asm volatile("tcgen05.commit.cta_group::1.mbarrier::arrive::one.shared::cluster.b64 [%0];" :: "r"(mb) : "memory")

#define MBAR_WAIT(mb, pa) do {                                                            \
    asm volatile("{\n\t.reg .pred P1;\n\t"                                                \
        "WL%=:\n\t"                                                                       \
        "mbarrier.try_wait.parity.acquire.cta.shared::cta.b64 P1, [%0], %1, 0x989680;\n\t"\
        "@P1 bra.uni WD%=;\n\t"                                                           \
        "bra.uni WL%=;\n\t"                                                               \
        "WD%=:\n\t}" :: "r"(mb), "r"(pa) : "memory");                                     \
} while (0)

#define LDTM_X32(r, a)                                                                    \
    asm volatile("tcgen05.ld.sync.aligned.32x32b.x32.b32 "                                \
        "{%0, %1, %2, %3, %4, %5, %6, %7, %8, %9, %10, %11, %12, %13, %14, %15, "         \
        " %16, %17, %18, %19, %20, %21, %22, %23, %24, %25, %26, %27, %28, %29, %30, %31}, [%32];" \
        : "=r"((r)[0]),  "=r"((r)[1]),  "=r"((r)[2]),  "=r"((r)[3]),                      \
          "=r"((r)[4]),  "=r"((r)[5]),  "=r"((r)[6]),  "=r"((r)[7]),                      \
          "=r"((r)[8]),  "=r"((r)[9]),  "=r"((r)[10]), "=r"((r)[11]),                     \
          "=r"((r)[12]), "=r"((r)[13]), "=r"((r)[14]), "=r"((r)[15]),                     \
          "=r"((r)[16]), "=r"((r)[17]), "=r"((r)[18]), "=r"((r)[19]),                     \
          "=r"((r)[20]), "=r"((r)[21]), "=r"((r)[22]), "=r"((r)[23]),                     \
          "=r"((r)[24]), "=r"((r)[25]), "=r"((r)[26]), "=r"((r)[27]),                     \
          "=r"((r)[28]), "=r"((r)[29]), "=r"((r)[30]), "=r"((r)[31])                      \
        : "r"(a))

__device__ __forceinline__ void split_pair(float a, float b, uint32_t& hi, uint32_t& lo) {
    uint32_t h;
    asm("cvt.rn.bf16x2.f32 %0, %1, %2;" : "=r"(h) : "f"(b), "f"(a));  // lo16=a, hi16=b
    float fa = __uint_as_float(h << 16);
    float fb = __uint_as_float(h & 0xffff0000u);
    uint32_t l;
    asm("cvt.rn.bf16x2.f32 %0, %1, %2;" : "=r"(l) : "f"(b - fb), "f"(a - fa));
    hi = h; lo = l;
}
__device__ __forceinline__ uint32_t f16x2(float a, float b) {   // lo16=a, hi16=b
    uint32_t r;
    asm("cvt.rn.f16x2.f32 %0, %1, %2;" : "=r"(r) : "f"(b), "f"(a));
    return r;
}

// prefetch 128x64 fp32 tile into 8 float4 regs (coalesced)
__device__ __forceinline__ void ldg8(const float* __restrict__ g, bool valid, int tid, float4* r) {
    #pragma unroll
    for (int it = 0; it < 8; it++) {
        int i = it * 256 + tid;
        int n = i >> 4, e4 = (i & 15) << 2;
        r[it] = valid ? *(const float4*)(g + (size_t)n * (SH * SD) + e4)
                      : make_float4(0.f, 0.f, 0.f, 0.f);
    }
}
// regs -> bf16 hi/lo, K-major SW128 128B rows (Q and K tiles)
__device__ __forceinline__ void sts_split(const float4* r, char* smc, int offhi, int offlo, int tid) {
    #pragma unroll
    for (int it = 0; it < 8; it++) {
        int i = it * 256 + tid;
        int n = i >> 4, e4 = (i & 15) << 2;
        uint32_t h0, l0, h1, l1;
        split_pair(r[it].x, r[it].y, h0, l0);
        split_pair(r[it].z, r[it].w, h1, l1);
        int boff = n * 128 + e4 * 2;
        int sw = boff ^ ((boff >> 3) & 0x70);
        *(uint2*)(smc + offhi + sw) = make_uint2(h0, h1);
        *(uint2*)(smc + offlo + sw) = make_uint2(l0, l1);
    }
}
// V regs [tok][dim] -> V^T fp16 (single precision term), blocked-atom K-major
// (atom=8x64, 8 atom-rows). Half the stores of the bf16 hi/lo version.
__device__ __forceinline__ void sts_vt(const float4* r, char* smc, int tid) {
    #pragma unroll
    for (int it = 0; it < 8; it++) {
        int i = it * 256 + tid;
        int n = i >> 4, e4 = (i & 15) << 2;
        float vals[4] = {r[it].x, r[it].y, r[it].z, r[it].w};
        #pragma unroll
        for (int j = 0; j < 4; j++) {
            int e = e4 + j;
            unsigned short hv;
            asm("{ .reg .f16 t; cvt.rn.f16.f32 t, %1; mov.b16 %0, t; }"
                : "=h"(hv) : "f"(vals[j]));
            int atom = (e >> 3) + ((n >> 6) << 3);
            int boff = atom * 1024 + (e & 7) * 128 + (n & 63) * 2;
            int sw = boff ^ ((boff >> 3) & 0x70);
            *(unsigned short*)(smc + OFF_VHI + sw) = hv;
        }
    }
}

__device__ __forceinline__ void issue_qk(uint32_t smb, uint32_t tS) {
    uint64_t aQh = desc_k(smb + OFF_QHI), aQl = desc_k(smb + OFF_QLO);
    uint64_t bKh = desc_k(smb + OFF_KHI), bKl = desc_k(smb + OFF_KLO);
    uint64_t as[3] = {aQh, aQh, aQl};
    uint64_t bs[3] = {bKh, bKl, bKh};
    uint32_t en = 0;
    #pragma unroll
    for (int tt = 0; tt < 3; tt++)
        #pragma unroll
        for (int k = 0; k < 4; k++) { mma_ss(tS, as[tt] + 2 * k, bs[tt] + 2 * k, IDESC_QK, en); en = 1; }
    COMMIT(smb + OFF_MBQ);
}
// single-term fp16 PV: O += P(fp16) @ V^T(fp16)
__device__ __forceinline__ void issue_pv(uint32_t smb, uint32_t tO, uint32_t en0) {
    uint64_t aP = desc_k(smb + OFF_PHI);
    uint64_t bV = desc_k(smb + OFF_VHI);
    uint32_t en = en0;
    #pragma unroll
    for (int k = 0; k < 8; k++) {
        mma_ss(tO, aP + (k >> 2) * 1024 + (k & 3) * 2,
                   bV + (k >> 2) * 512  + (k & 3) * 2, IDESC_PV, en);
        en = 1;
    }
    COMMIT(smb + OFF_MBP);
}
#endif  // HAS_TC

__global__ void __launch_bounds__(256, 1)
wk_tc(const float* __restrict__ Q, const float* __restrict__ K,
      const float* __restrict__ V, float* __restrict__ Out, float* __restrict__ Attn)
{
#if HAS_TC
    extern __shared__ char smc[];
    const uint32_t smb = smem_u32(smc);
    const int tid = threadIdx.x;
    const int w = tid >> 5, lane = tid & 31;
    const int sp = w & 3, ch = w >> 2;
    const int m = sp * 32 + lane;

    const int blk = blockIdx.x;
    const int mh = blk & 1, h = (blk >> 1) & 7, c = (blk >> 4) & 31, b = blk >> 9;
    const int q0 = c * 256 + mh * 128;

    if (w == 0) {
        asm volatile("tcgen05.alloc.cta_group::1.sync.aligned.shared::cta.b32 [%0], %1;"
                     :: "r"(smb), "r"(512) : "memory");
        asm volatile("tcgen05.relinquish_alloc_permit.cta_group::1.sync.aligned;");
    }
    if (tid == 0) {
        asm volatile("mbarrier.init.shared.b64 [%0], %1;" :: "r"(smb + OFF_MBQ), "r"(1) : "memory");
        asm volatile("mbarrier.init.shared.b64 [%0], %1;" :: "r"(smb + OFF_MBP), "r"(1) : "memory");
    }
    __syncthreads();
    uint32_t tmem;
    asm volatile("ld.shared.b32 %0, [%1];" : "=r"(tmem) : "r"(smb));
    const uint32_t tS0 = tmem, tS1 = tmem + 128, tO = tmem + 256;

    // Q tile resident all kernel
    {
        float4 qr[8];
        ldg8(Q + ((size_t)(b * SS + q0) * SH + h) * SD, true, tid, qr);
        sts_split(qr, smc, OFF_QHI, OFF_QLO, tid);
    }

    auto kvalid = [&](int t) { int ck = c + (t >> 1) - 1; return (ck >= 0) && (ck < SC); };
    auto kvoff = [&](int t) -> size_t {
        int ck = c + (t >> 1) - 1;
        return ((size_t)(b * SS + ck * 256 + (t & 1) * 128) * SH + h) * SD;
    };

    int phQ = 0, phP = 0;
    float rsum = 0.f;
    float4 kreg[8], vreg[8];

    // ================= pass A: rowsums =================
    ldg8(K + kvoff(0), kvalid(0), tid, kreg);
    sts_split(kreg, smc, OFF_KHI, OFF_KLO, tid);
    FENCE_ASYNC();
    __syncthreads();
    if (w == 0 && elect1()) { TM_FENCE_A(); issue_qk(smb, tS0); }
    ldg8(K + kvoff(1), kvalid(1), tid, kreg);

    for (int t = 0; t < 6; t++) {
        MBAR_WAIT(smb + OFF_MBQ, phQ & 1); phQ++;     // QK_t done
        TM_FENCE_A();
        if (t < 5) {
            sts_split(kreg, smc, OFF_KHI, OFF_KLO, tid);   // K_{t+1} (K buf free)
            FENCE_ASYNC();
        }
        __syncthreads();
        if (t < 5 && w == 0 && elect1()) { TM_FENCE_A(); issue_qk(smb, ((t + 1) & 1) ? tS1 : tS0); }
        if (t < 4) ldg8(K + kvoff(t + 2), kvalid(t + 2), tid, kreg);

        const uint32_t tS = (t & 1) ? tS1 : tS0;
        #pragma unroll
        for (int g = 0; g < 2; g++) {
            uint32_t r[32];
            LDTM_X32(r, tS + ch * 64 + g * 32);
            TM_WAIT_LD();
            #pragma unroll
            for (int q = 0; q < 32; q++) rsum += __expf(__uint_as_float(r[q]));
        }
        TM_FENCE_B();
    }

    // rowsum combine -> inv
    *(float*)(smc + OFF_RS + (ch * 128 + m) * 4) = rsum;
    __syncthreads();
    if (tid < 128) {
        float s = *(float*)(smc + OFF_RS + tid * 4) + *(float*)(smc + OFF_RS + (128 + tid) * 4);
        *(float*)(smc + OFF_INV + tid * 4) = 1.0f / s;
    }
    __syncthreads();
    const float inv = *(float*)(smc + OFF_INV + m * 4);
    char* stg = smc + OFF_STG + ch * STG_WG;

    // ================= pass B: attn + PV =================
    ldg8(K + kvoff(0), kvalid(0), tid, kreg);
    sts_split(kreg, smc, OFF_KHI, OFF_KLO, tid);
    FENCE_ASYNC();
    __syncthreads();
    if (w == 0 && elect1()) { TM_FENCE_A(); issue_qk(smb, tS0); }
    ldg8(V + kvoff(0), kvalid(0), tid, vreg);

    for (int t = 0; t < 6; t++) {
        if (t > 0) { MBAR_WAIT(smb + OFF_MBP, phP & 1); phP++; TM_FENCE_A(); }  // PV_{t-1}
        sts_vt(vreg, smc, tid);                            // V_t (V buf free)
        if (t < 5) ldg8(K + kvoff(t + 1), kvalid(t + 1), tid, kreg);

        MBAR_WAIT(smb + OFF_MBQ, phQ & 1); phQ++;          // QK_t done
        TM_FENCE_A();
        const uint32_t tS = (t & 1) ? tS1 : tS0;
        float* abase = Attn + ((size_t)(b * SS + q0) * SH + h) * SNW + t * 128 + ch * 64;

        #pragma unroll
        for (int g = 0; g < 2; g++) {
            uint32_t r[32];
            LDTM_X32(r, tS + ch * 64 + g * 32);
            TM_WAIT_LD();
            float p[32];
            #pragma unroll
            for (int q = 0; q < 32; q++) p[q] = __expf(__uint_as_float(r[q])) * inv;
            // normalized P -> fp16 smem (blocked-atom layout), single precision term
            #pragma unroll
            for (int q = 0; q < 8; q++) {
                int col = ch * 64 + g * 32 + q * 4;
                uint32_t h0 = f16x2(p[4*q],   p[4*q+1]);
                uint32_t h1 = f16x2(p[4*q+2], p[4*q+3]);
                int atom = (m >> 3) + ((col >> 6) << 4);
                int boff = atom * 1024 + (m & 7) * 128 + (col & 63) * 2;
                int sw = boff ^ ((boff >> 3) & 0x70);
                *(uint2*)(smc + OFF_PHI + sw) = make_uint2(h0, h1);
            }
            #pragma unroll
            for (int q = 0; q < 8; q++)
                *(float4*)(stg + (m * STG_STRIDE + q * 4) * 4) =
                    make_float4(p[4*q], p[4*q+1], p[4*q+2], p[4*q+3]);
            TM_FENCE_B();
            if (g == 0) {
                __syncthreads();
                // attn write g=0 (cols +0..31)
                #pragma unroll
                for (int it = 0; it < 8; it++) {
                    int row = it * 16 + sp * 4 + (lane >> 3);
                    int c4 = (lane & 7) << 2;
                    float4 vv = *(const float4*)(stg + (row * STG_STRIDE + c4) * 4);
                    *(float4*)(abase + (size_t)row * (SH * SNW) + c4) = vv;
                }
                __syncthreads();   // all g0 staging reads done before g1 overwrites
            }
        }
        FENCE_ASYNC();
        __syncthreads();                                   // P smem + V smem complete
        if (w == 0 && elect1()) { TM_FENCE_A(); issue_pv(smb, tO, t > 0); }

        // attn write g=1 (cols +32..63) — overlaps PV_t
        #pragma unroll
        for (int it = 0; it < 8; it++) {
            int row = it * 16 + sp * 4 + (lane >> 3);
            int c4 = (lane & 7) << 2;
            float4 vv = *(const float4*)(stg + (row * STG_STRIDE + c4) * 4);
            *(float4*)(abase + (size_t)row * (SH * SNW) + 32 + c4) = vv;
        }
        if (t < 5) {
            sts_split(kreg, smc, OFF_KHI, OFF_KLO, tid);   // K_{t+1} (QK_t done; PV doesn't read K)
            ldg8(V + kvoff(t + 1), kvalid(t + 1), tid, vreg);
            FENCE_ASYNC();
            __syncthreads();
            if (w == 0 && elect1()) { TM_FENCE_A(); issue_qk(smb, ((t + 1) & 1) ? tS1 : tS0); }
        }
    }
    MBAR_WAIT(smb + OFF_MBP, phP & 1); phP++;              // PV_5
    TM_FENCE_A();

    {   // O epilogue (already normalized)
        uint32_t r[32];
        LDTM_X32(r, tO + ch * 32);
        TM_WAIT_LD();
        TM_FENCE_B();
        float* orow = Out + ((size_t)(b * SS + q0 + m) * SH + h) * SD + ch * 32;
        #pragma unroll
        for (int q = 0; q < 8; q++)
            *(float4*)(orow + q * 4) = make_float4(
                __uint_as_float(r[4*q]),   __uint_as_float(r[4*q+1]),
                __uint_as_float(r[4*q+2]), __uint_as_float(r[4*q+3]));
    }
    __syncthreads();
    if (tid == 0) {
        asm volatile("mbarrier.inval.shared.b64 [%0];" :: "r"(smb + OFF_MBQ) : "memory");
        asm volatile("mbarrier.inval.shared.b64 [%0];" :: "r"(smb + OFF_MBP) : "memory");
    }
    __syncthreads();
    if (w == 0)
        asm volatile("tcgen05.dealloc.cta_group::1.sync.aligned.b32 %0, %1;" :: "r"(tmem), "r"(512));
#endif  // HAS_TC
}

// ================= SIMT fallback =================
#define MT 32
#define NTILE 128
#define KSTR 68
#define SMEM_FLOATS (MT*SNW + MT*KSTR + NTILE*KSTR + MT)

__global__ void __launch_bounds__(256, 1)
wk_simt(const float* __restrict__ Q, const float* __restrict__ K,
        const float* __restrict__ V, float* __restrict__ Out, float* __restrict__ Attn)
{
    extern __shared__ float sm[];
    float* sP = sm;
    float* sQ = sP + MT * SNW;
    float* sKV = sQ + MT * KSTR;
    float* sSum = sKV + NTILE * KSTR;
    const int tid = threadIdx.x, tx = tid & 31, ty = tid >> 5;
    const int blk = blockIdx.x;
    const int mblk = blk & 7, h = (blk >> 3) & 7, c = (blk >> 6) & 31, b = blk >> 11;
    const int q0 = c * 256 + mblk * MT;
    if (tid < MT) sSum[tid] = 0.0f;
    for (int i = tid; i < MT * 16; i += 256) {
        int mm = i >> 4, d4 = (i & 15) << 2;
        *(float4*)&sQ[mm * KSTR + d4] = *(const float4*)&Q[((((size_t)b*SS)+q0+mm)*SH+h)*SD + d4];
    }
    for (int t = 0; t < 6; t++) {
        int ck = c + (t >> 1) - 1, koff = (t & 1) * NTILE;
        bool valid = (ck >= 0) && (ck < SC);
        for (int i = tid; i < NTILE * 16; i += 256) {
            int n = i >> 4, d4 = (i & 15) << 2;
            float4 kv = make_float4(0.f,0.f,0.f,0.f);
            if (valid) kv = *(const float4*)&K[((((size_t)b*SS)+ck*256+koff+n)*SH+h)*SD + d4];
            *(float4*)&sKV[n * KSTR + d4] = kv;
        }
        __syncthreads();
        float acc[4][4];
        #pragma unroll
        for (int mi = 0; mi < 4; mi++) { acc[mi][0]=acc[mi][1]=acc[mi][2]=acc[mi][3]=0.f; }
        #pragma unroll
        for (int kk = 0; kk < SD; kk += 4) {
            float4 qv[4], kv[4];
            #pragma unroll
            for (int mi = 0; mi < 4; mi++) qv[mi] = *(const float4*)&sQ[(ty*4+mi)*KSTR + kk];
            #pragma unroll
            for (int ni = 0; ni < 4; ni++) kv[ni] = *(const float4*)&sKV[(tx+32*ni)*KSTR + kk];
            #pragma unroll
            for (int mi = 0; mi < 4; mi++)
                #pragma unroll
                for (int ni = 0; ni < 4; ni++)
                    acc[mi][ni] += qv[mi].x*kv[ni].x + qv[mi].y*kv[ni].y
                                 + qv[mi].z*kv[ni].z + qv[mi].w*kv[ni].w;
        }
        #pragma unroll
        for (int mi = 0; mi < 4; mi++) {
            int mm = ty*4+mi;
            float rs = 0.f;
            #pragma unroll
            for (int ni = 0; ni < 4; ni++) {
                float p = __expf(acc[mi][ni]);
                sP[mm*SNW + t*NTILE + tx + 32*ni] = p;
                rs += p;
            }
            #pragma unroll
            for (int off = 16; off > 0; off >>= 1) rs += __shfl_xor_sync(0xffffffffu, rs, off);
            if (tx == 0) sSum[mm] += rs;
        }
        __syncthreads();
    }
    if (tid < MT) sSum[tid] = 1.0f / sSum[tid];
    __syncthreads();
    #pragma unroll 4
    for (int i = tid; i < MT * 192; i += 256) {
        int mm = i / 192, j4 = (i - mm*192) << 2;
        float4 p = *(const float4*)&sP[mm*SNW + j4];
        float iv = sSum[mm];
        p.x*=iv; p.y*=iv; p.z*=iv; p.w*=iv;
        *(float4*)&Attn[((((size_t)b*SS)+q0+mm)*SH+h)*SNW + j4] = p;
    }
    float acco[4][2];
    #pragma unroll
    for (int mi = 0; mi < 4; mi++) { acco[mi][0]=0.f; acco[mi][1]=0.f; }
    for (int t = 0; t < 6; t++) {
        int ck = c + (t >> 1) - 1, koff = (t & 1) * NTILE;
        bool valid = (ck >= 0) && (ck < SC);
        __syncthreads();
        for (int i = tid; i < NTILE * 16; i += 256) {
            int n = i >> 4, d4 = (i & 15) << 2;
            float4 vv = make_float4(0.f,0.f,0.f,0.f);
            if (valid) vv = *(const float4*)&V[((((size_t)b*SS)+ck*256+koff+n)*SH+h)*SD + d4];
            *(float4*)&sKV[n * KSTR + d4] = vv;
        }
        __syncthreads();
        #pragma unroll 8
        for (int kk = 0; kk < NTILE; kk += 4) {
            float4 pv[4];
            #pragma unroll
            for (int mi = 0; mi < 4; mi++) pv[mi] = *(const float4*)&sP[(ty*4+mi)*SNW + t*NTILE + kk];
            #pragma unroll
            for (int u = 0; u < 4; u++) {
                float va0 = sKV[(kk+u)*KSTR + tx], va1 = sKV[(kk+u)*KSTR + tx + 32];
                #pragma unroll
                for (int mi = 0; mi < 4; mi++) {
                    float pm = (u==0)?pv[mi].x:(u==1)?pv[mi].y:(u==2)?pv[mi].z:pv[mi].w;
                    acco[mi][0] += pm*va0;
                    acco[mi][1] += pm*va1;
                }
            }
        }
    }
    #pragma unroll
    for (int mi = 0; mi < 4; mi++) {
        int mm = ty*4+mi;
        float iv = sSum[mm];
        float* op = &Out[((((size_t)b*SS)+q0+mm)*SH+h)*SD];
        op[tx] = acco[mi][0]*iv;
        op[tx+32] = acco[mi][1]*iv;
    }
}

extern "C" void kernel_launch(void* const* d_in, const int* in_sizes, int n_in,
                              void* d_out, int out_size)
{
    const float* q = (const float*)d_in[0];
    const float* k = (const float*)d_in[1];
    const float* v = (const float*)d_in[2];
    float* out  = (float*)d_out;
    float* attn = out + (size_t)SB * SS * SH * SD;   // [output | attention]

    cudaFuncAttributes fa{};
    cudaFuncGetAttributes(&fa, wk_tc);
    if (fa.numRegs >= 40) {
        cudaFuncSetAttribute(wk_tc, cudaFuncAttributeMaxDynamicSharedMemorySize, SMEM_TC);
        wk_tc<<<SB * SC * SH * 2, 256, SMEM_TC>>>(q, k, v, out, attn);
    } else {
        const int smem = SMEM_FLOATS * sizeof(float);
        cudaFuncSetAttribute(wk_simt, cudaFuncAttributeMaxDynamicSharedMemorySize, smem);
        wk_simt<<<SB * SC * SH * 8, 256, smem>>>(q, k, v, out, attn);
    }
}

// round 12
// speedup vs baseline: 1.7805x; 1.1732x over previous
#include <cuda_runtime.h>
#include <cuda_bf16.h>
#include <cuda_fp16.h>
#include <cstdint>

#define SB 2
#define SS 8192
#define SH 8
#define SD 64
#define SC 32
#define SNW 768

#if defined(__CUDA_ARCH_FEAT_SM103_ALL) || defined(__CUDA_ARCH_FEAT_SM100_ALL) || \
    defined(__CUDA_ARCH_FEAT_SM101_ALL) || defined(__CUDA_ARCH_FEAT_SM110_ALL)
#define HAS_TC 1
#else
#define HAS_TC 0
#endif

// smem layout (bytes)
#define OFF_MBQ   8
#define OFF_MBP   16
#define OFF_RS    32
#define OFF_INV   1056
#define OFF_QHI   2048
#define OFF_QLO   18432
#define OFF_KHI   34816
#define OFF_KLO   51200
#define OFF_VHI   67584
#define OFF_PHI   100352
#define SMEM_TC   165888

#define IDESC_QK 0x08200490u   /* M=128 N=128, bf16 inputs */
#define IDESC_PV 0x08100010u   /* M=128 N=64,  fp16 inputs */

#if HAS_TC
__device__ __forceinline__ uint32_t smem_u32(const void* p) {
    uint32_t a;
    asm("{ .reg .u64 t; cvta.to.shared.u64 t, %1; cvt.u32.u64 %0, t; }" : "=r"(a) : "l"(p));
    return a;
}
__device__ __forceinline__ uint32_t elect1() {
    uint32_t p;
    asm volatile("{ .reg .pred p; elect.sync _|p, 0xFFFFFFFF; selp.b32 %0, 1, 0, p; }" : "=r"(p));
    return p;
}
__device__ __forceinline__ uint64_t desc_k(uint32_t a) {   // K-major SW128: LBO=1, SBO=64
    return (2ull << 61) | (1ull << 46) | (64ull << 32) | (1ull << 16) | ((a >> 4) & 0x3FFF);
}
__device__ __forceinline__ void mma_ss(uint32_t d, uint64_t a, uint64_t b, uint32_t id, uint32_t en) {
    asm volatile(
        "{\n\t.reg .pred p;\n\tsetp.ne.u32 p, %4, 0;\n\t"
        "tcgen05.mma.cta_group::1.kind::f16 [%0], %1, %2, %3, {%5, %5, %5, %5}, p;\n\t}"
        :: "r"(d), "l"(a), "l"(b), "r"(id), "r"(en), "r"(0u) : "memory");
}
#define TM_FENCE_A() asm volatile("tcgen05.fence::after_thread_sync;" ::: "memory")
#define TM_FENCE_B() asm volatile("tcgen05.fence::before_thread_sync;" ::: "memory")
#define TM_WAIT_LD() asm volatile("tcgen05.wait::ld.sync.aligned;" ::: "memory")
#define FENCE_ASYNC() asm volatile("fence.proxy.async.shared::cta;" ::: "memory")
#define COMMIT(mb) asm volatile("tcgen05.commit.cta_group::1.mbarrier::arrive::one.shared::cluster.b64 [%0];" :: "r"(mb) : "memory")

#define MBAR_WAIT(mb, pa) do {                                                            \
    asm volatile("{\n\t.reg .pred P1;\n\t"                                                \
        "WL%=:\n\t"                                                                       \
        "mbarrier.try_wait.parity.acquire.cta.shared::cta.b64 P1, [%0], %1, 0x989680;\n\t"\
        "@P1 bra.uni WD%=;\n\t"                                                           \
        "bra.uni WL%=;\n\t"                                                               \
        "WD%=:\n\t}" :: "r"(mb), "r"(pa) : "memory");                                     \
} while (0)

#define LDTM_X32(r, a)                                                                    \
    asm volatile("tcgen05.ld.sync.aligned.32x32b.x32.b32 "                                \
        "{%0, %1, %2, %3, %4, %5, %6, %7, %8, %9, %10, %11, %12, %13, %14, %15, "         \
        " %16, %17, %18, %19, %20, %21, %22, %23, %24, %25, %26, %27, %28, %29, %30, %31}, [%32];" \
        : "=r"((r)[0]),  "=r"((r)[1]),  "=r"((r)[2]),  "=r"((r)[3]),                      \
          "=r"((r)[4]),  "=r"((r)[5]),  "=r"((r)[6]),  "=r"((r)[7]),                      \
          "=r"((r)[8]),  "=r"((r)[9]),  "=r"((r)[10]), "=r"((r)[11]),                     \
          "=r"((r)[12]), "=r"((r)[13]), "=r"((r)[14]), "=r"((r)[15]),                     \
          "=r"((r)[16]), "=r"((r)[17]), "=r"((r)[18]), "=r"((r)[19]),                     \
          "=r"((r)[20]), "=r"((r)[21]), "=r"((r)[22]), "=r"((r)[23]),                     \
          "=r"((r)[24]), "=r"((r)[25]), "=r"((r)[26]), "=r"((r)[27]),                     \
          "=r"((r)[28]), "=r"((r)[29]), "=r"((r)[30]), "=r"((r)[31])                      \
        : "r"(a))

__device__ __forceinline__ void split_pair(float a, float b, uint32_t& hi, uint32_t& lo) {
    uint32_t h;
    asm("cvt.rn.bf16x2.f32 %0, %1, %2;" : "=r"(h) : "f"(b), "f"(a));  // lo16=a, hi16=b
    float fa = __uint_as_float(h << 16);
    float fb = __uint_as_float(h & 0xffff0000u);
    uint32_t l;
    asm("cvt.rn.bf16x2.f32 %0, %1, %2;" : "=r"(l) : "f"(b - fb), "f"(a - fa));
    hi = h; lo = l;
}
__device__ __forceinline__ uint32_t f16x2(float a, float b) {   // lo16=a, hi16=b
    uint32_t r;
    asm("cvt.rn.f16x2.f32 %0, %1, %2;" : "=r"(r) : "f"(b), "f"(a));
    return r;
}

// prefetch 128x64 fp32 tile into 8 float4 regs (coalesced)
__device__ __forceinline__ void ldg8(const float* __restrict__ g, bool valid, int tid, float4* r) {
    #pragma unroll
    for (int it = 0; it < 8; it++) {
        int i = it * 256 + tid;
        int n = i >> 4, e4 = (i & 15) << 2;
        r[it] = valid ? *(const float4*)(g + (size_t)n * (SH * SD) + e4)
                      : make_float4(0.f, 0.f, 0.f, 0.f);
    }
}
// regs -> bf16 hi/lo, K-major SW128 128B rows (Q and K tiles)
__device__ __forceinline__ void sts_split(const float4* r, char* smc, int offhi, int offlo, int tid) {
    #pragma unroll
    for (int it = 0; it < 8; it++) {
        int i = it * 256 + tid;
        int n = i >> 4, e4 = (i & 15) << 2;
        uint32_t h0, l0, h1, l1;
        split_pair(r[it].x, r[it].y, h0, l0);
        split_pair(r[it].z, r[it].w, h1, l1);
        int boff = n * 128 + e4 * 2;
        int sw = boff ^ ((boff >> 3) & 0x70);
        *(uint2*)(smc + offhi + sw) = make_uint2(h0, h1);
        *(uint2*)(smc + offlo + sw) = make_uint2(l0, l1);
    }
}
// V regs [tok][dim] -> V^T fp16, blocked-atom K-major (atom=8x64, 8 atom-rows)
__device__ __forceinline__ void sts_vt(const float4* r, char* smc, int tid) {
    #pragma unroll
    for (int it = 0; it < 8; it++) {
        int i = it * 256 + tid;
        int n = i >> 4, e4 = (i & 15) << 2;
        float vals[4] = {r[it].x, r[it].y, r[it].z, r[it].w};
        #pragma unroll
        for (int j = 0; j < 4; j++) {
            int e = e4 + j;
            unsigned short hv;
            asm("{ .reg .f16 t; cvt.rn.f16.f32 t, %1; mov.b16 %0, t; }"
                : "=h"(hv) : "f"(vals[j]));
            int atom = (e >> 3) + ((n >> 6) << 3);
            int boff = atom * 1024 + (e & 7) * 128 + (n & 63) * 2;
            int sw = boff ^ ((boff >> 3) & 0x70);
            *(unsigned short*)(smc + OFF_VHI + sw) = hv;
        }
    }
}

__device__ __forceinline__ void issue_qk(uint32_t smb, uint32_t tS) {
    uint64_t aQh = desc_k(smb + OFF_QHI), aQl = desc_k(smb + OFF_QLO);
    uint64_t bKh = desc_k(smb + OFF_KHI), bKl = desc_k(smb + OFF_KLO);
    uint64_t as[3] = {aQh, aQh, aQl};
    uint64_t bs[3] = {bKh, bKl, bKh};
    uint32_t en = 0;
    #pragma unroll
    for (int tt = 0; tt < 3; tt++)
        #pragma unroll
        for (int k = 0; k < 4; k++) { mma_ss(tS, as[tt] + 2 * k, bs[tt] + 2 * k, IDESC_QK, en); en = 1; }
    COMMIT(smb + OFF_MBQ);
}
// single-term fp16 PV: O += P(fp16) @ V^T(fp16)
__device__ __forceinline__ void issue_pv(uint32_t smb, uint32_t tO, uint32_t en0) {
    uint64_t aP = desc_k(smb + OFF_PHI);
    uint64_t bV = desc_k(smb + OFF_VHI);
    uint32_t en = en0;
    #pragma unroll
    for (int k = 0; k < 8; k++) {
        mma_ss(tO, aP + (k >> 2) * 1024 + (k & 3) * 2,
                   bV + (k >> 2) * 512  + (k & 3) * 2, IDESC_PV, en);
        en = 1;
    }
    COMMIT(smb + OFF_MBP);
}
#endif  // HAS_TC

__global__ void __launch_bounds__(256, 1)
wk_tc(const float* __restrict__ Q, const float* __restrict__ K,
      const float* __restrict__ V, float* __restrict__ Out, float* __restrict__ Attn)
{
#if HAS_TC
    extern __shared__ char smc[];
    const uint32_t smb = smem_u32(smc);
    const int tid = threadIdx.x;
    const int w = tid >> 5, lane = tid & 31;
    const int sp = w & 3, ch = w >> 2;
    const int m = sp * 32 + lane;

    const int blk = blockIdx.x;
    const int mh = blk & 1, h = (blk >> 1) & 7, c = (blk >> 4) & 31, b = blk >> 9;
    const int q0 = c * 256 + mh * 128;

    if (w == 0) {
        asm volatile("tcgen05.alloc.cta_group::1.sync.aligned.shared::cta.b32 [%0], %1;"
                     :: "r"(smb), "r"(512) : "memory");
        asm volatile("tcgen05.relinquish_alloc_permit.cta_group::1.sync.aligned;");
    }
    if (tid == 0) {
        asm volatile("mbarrier.init.shared.b64 [%0], %1;" :: "r"(smb + OFF_MBQ), "r"(1) : "memory");
        asm volatile("mbarrier.init.shared.b64 [%0], %1;" :: "r"(smb + OFF_MBP), "r"(1) : "memory");
    }
    __syncthreads();
    uint32_t tmem;
    asm volatile("ld.shared.b32 %0, [%1];" : "=r"(tmem) : "r"(smb));
    const uint32_t tS0 = tmem, tS1 = tmem + 128, tO = tmem + 256;

    // Q tile resident all kernel
    {
        float4 qr[8];
        ldg8(Q + ((size_t)(b * SS + q0) * SH + h) * SD, true, tid, qr);
        sts_split(qr, smc, OFF_QHI, OFF_QLO, tid);
    }

    auto kvalid = [&](int t) { int ck = c + (t >> 1) - 1; return (ck >= 0) && (ck < SC); };
    auto kvoff = [&](int t) -> size_t {
        int ck = c + (t >> 1) - 1;
        return ((size_t)(b * SS + ck * 256 + (t & 1) * 128) * SH + h) * SD;
    };

    int phQ = 0, phP = 0;
    float rsum = 0.f;
    float4 kreg[8], vreg[8];

    // ================= pass A: rowsums =================
    ldg8(K + kvoff(0), kvalid(0), tid, kreg);
    sts_split(kreg, smc, OFF_KHI, OFF_KLO, tid);
    FENCE_ASYNC();
    __syncthreads();
    if (w == 0 && elect1()) { TM_FENCE_A(); issue_qk(smb, tS0); }
    ldg8(K + kvoff(1), kvalid(1), tid, kreg);

    for (int t = 0; t < 6; t++) {
        MBAR_WAIT(smb + OFF_MBQ, phQ & 1); phQ++;     // QK_t done
        TM_FENCE_A();
        if (t < 5) {
            sts_split(kreg, smc, OFF_KHI, OFF_KLO, tid);   // K_{t+1} (K buf free)
            FENCE_ASYNC();
        }
        __syncthreads();
        if (t < 5 && w == 0 && elect1()) { TM_FENCE_A(); issue_qk(smb, ((t + 1) & 1) ? tS1 : tS0); }
        if (t < 4) ldg8(K + kvoff(t + 2), kvalid(t + 2), tid, kreg);

        const uint32_t tS = (t & 1) ? tS1 : tS0;
        #pragma unroll
        for (int g = 0; g < 2; g++) {
            uint32_t r[32];
            LDTM_X32(r, tS + ch * 64 + g * 32);
            TM_WAIT_LD();
            #pragma unroll
            for (int q = 0; q < 32; q++) rsum += __expf(__uint_as_float(r[q]));
        }
        TM_FENCE_B();
    }
    // after pass A: tS0 holds S_4, tS1 holds S_5 (reused in pass B steps 0,1)

    // rowsum combine -> inv
    *(float*)(smc + OFF_RS + (ch * 128 + m) * 4) = rsum;
    __syncthreads();
    if (tid < 128) {
        float s = *(float*)(smc + OFF_RS + tid * 4) + *(float*)(smc + OFF_RS + (128 + tid) * 4);
        *(float*)(smc + OFF_INV + tid * 4) = 1.0f / s;
    }
    __syncthreads();
    const float inv = *(float*)(smc + OFF_INV + m * 4);

    // ================= pass B: tiles in order {4,5,0,1,2,3} =================
    // steps 0,1 use cached S_4/S_5 (no QK); QK recomputed only for tiles 0..3.
    ldg8(V + kvoff(4), kvalid(4), tid, vreg);          // V for step 0
    const int tmap[6] = {4, 5, 0, 1, 2, 3};

    #pragma unroll
    for (int i = 0; i < 6; i++) {
        const int t = tmap[i];
        if (i > 0) { MBAR_WAIT(smb + OFF_MBP, phP & 1); phP++; TM_FENCE_A(); }  // PV_{i-1}
        sts_vt(vreg, smc, tid);                        // V_t (V buf + PHI free)
        if (i < 4) ldg8(K + kvoff(tmap[i + 2]), kvalid(tmap[i + 2]), tid, kreg);
        if (i == 5) { MBAR_WAIT(smb + OFF_MBQ, phQ & 1); phQ++; TM_FENCE_A(); } // QK_{tmap[5]}

        const uint32_t tS = (i & 1) ? tS1 : tS0;
        #pragma unroll
        for (int g = 0; g < 2; g++) {
            uint32_t r[32];
            LDTM_X32(r, tS + ch * 64 + g * 32);
            TM_WAIT_LD();
            float p[32];
            #pragma unroll
            for (int q = 0; q < 32; q++) p[q] = __expf(__uint_as_float(r[q])) * inv;
            #pragma unroll
            for (int q = 0; q < 8; q++) {
                int col = ch * 64 + g * 32 + q * 4;
                uint32_t h0 = f16x2(p[4*q],   p[4*q+1]);
                uint32_t h1 = f16x2(p[4*q+2], p[4*q+3]);
                int atom = (m >> 3) + ((col >> 6) << 4);
                int boff = atom * 1024 + (m & 7) * 128 + (col & 63) * 2;
                int sw = boff ^ ((boff >> 3) & 0x70);
                *(uint2*)(smc + OFF_PHI + sw) = make_uint2(h0, h1);
            }
        }
        TM_FENCE_B();
        FENCE_ASYNC();
        __syncthreads();                               // PHI (all warps) + V complete
        if (w == 0 && elect1()) { TM_FENCE_A(); issue_pv(smb, tO, i > 0); }

        // attn write straight from PHI fp16 (overlaps PV_i); warp w -> rows w*16..+15
        {
            float* abase = Attn + ((size_t)(b * SS + q0) * SH + h) * SNW + t * 128;
            const int col = lane * 4;
            const int atomc = (col >> 6) << 4;
            #pragma unroll
            for (int it2 = 0; it2 < 16; it2++) {
                int row = w * 16 + it2;
                int atom = (row >> 3) + atomc;
                int boff = atom * 1024 + (row & 7) * 128 + (col & 63) * 2;
                int sw = boff ^ ((boff >> 3) & 0x70);
                uint2 hv = *(uint2*)(smc + OFF_PHI + sw);
                float2 f0 = __half22float2(*(__half2*)&hv.x);
                float2 f1 = __half22float2(*(__half2*)&hv.y);
                *(float4*)(abase + (size_t)row * (SH * SNW) + col) =
                    make_float4(f0.x, f0.y, f1.x, f1.y);
            }
        }
        if (i < 4) {
            if (i >= 1) { MBAR_WAIT(smb + OFF_MBQ, phQ & 1); phQ++; TM_FENCE_A(); } // QK_{tmap[i+1]} done -> K buf free
            sts_split(kreg, smc, OFF_KHI, OFF_KLO, tid);   // K_{tmap[i+2]}
        }
        if (i < 5) ldg8(V + kvoff(tmap[i + 1]), kvalid(tmap[i + 1]), tid, vreg);
        if (i < 4) {
            FENCE_ASYNC();
            __syncthreads();
            if (w == 0 && elect1()) { TM_FENCE_A(); issue_qk(smb, (i & 1) ? tS1 : tS0); }
        }
    }
    MBAR_WAIT(smb + OFF_MBP, phP & 1); phP++;          // PV_5
    TM_FENCE_A();

    {   // O epilogue (already normalized)
        uint32_t r[32];
        LDTM_X32(r, tO + ch * 32);
        TM_WAIT_LD();
        TM_FENCE_B();
        float* orow = Out + ((size_t)(b * SS + q0 + m) * SH + h) * SD + ch * 32;
        #pragma unroll
        for (int q = 0; q < 8; q++)
            *(float4*)(orow + q * 4) = make_float4(
                __uint_as_float(r[4*q]),   __uint_as_float(r[4*q+1]),
                __uint_as_float(r[4*q+2]), __uint_as_float(r[4*q+3]));
    }
    __syncthreads();
    if (tid == 0) {
        asm volatile("mbarrier.inval.shared.b64 [%0];" :: "r"(smb + OFF_MBQ) : "memory");
        asm volatile("mbarrier.inval.shared.b64 [%0];" :: "r"(smb + OFF_MBP) : "memory");
    }
    __syncthreads();
    if (w == 0)
        asm volatile("tcgen05.dealloc.cta_group::1.sync.aligned.b32 %0, %1;" :: "r"(tmem), "r"(512));
#endif  // HAS_TC
}

// ================= SIMT fallback =================
#define MT 32
#define NTILE 128
#define KSTR 68
#define SMEM_FLOATS (MT*SNW + MT*KSTR + NTILE*KSTR + MT)

__global__ void __launch_bounds__(256, 1)
wk_simt(const float* __restrict__ Q, const float* __restrict__ K,
        const float* __restrict__ V, float* __restrict__ Out, float* __restrict__ Attn)
{
    extern __shared__ float sm[];
    float* sP = sm;
    float* sQ = sP + MT * SNW;
    float* sKV = sQ + MT * KSTR;
    float* sSum = sKV + NTILE * KSTR;
    const int tid = threadIdx.x, tx = tid & 31, ty = tid >> 5;
    const int blk = blockIdx.x;
    const int mblk = blk & 7, h = (blk >> 3) & 7, c = (blk >> 6) & 31, b = blk >> 11;
    const int q0 = c * 256 + mblk * MT;
    if (tid < MT) sSum[tid] = 0.0f;
    for (int i = tid; i < MT * 16; i += 256) {
        int mm = i >> 4, d4 = (i & 15) << 2;
        *(float4*)&sQ[mm * KSTR + d4] = *(const float4*)&Q[((((size_t)b*SS)+q0+mm)*SH+h)*SD + d4];
    }
    for (int t = 0; t < 6; t++) {
        int ck = c + (t >> 1) - 1, koff = (t & 1) * NTILE;
        bool valid = (ck >= 0) && (ck < SC);
        for (int i = tid; i < NTILE * 16; i += 256) {
            int n = i >> 4, d4 = (i & 15) << 2;
            float4 kv = make_float4(0.f,0.f,0.f,0.f);
            if (valid) kv = *(const float4*)&K[((((size_t)b*SS)+ck*256+koff+n)*SH+h)*SD + d4];
            *(float4*)&sKV[n * KSTR + d4] = kv;
        }
        __syncthreads();
        float acc[4][4];
        #pragma unroll
        for (int mi = 0; mi < 4; mi++) { acc[mi][0]=acc[mi][1]=acc[mi][2]=acc[mi][3]=0.f; }
        #pragma unroll
        for (int kk = 0; kk < SD; kk += 4) {
            float4 qv[4], kv[4];
            #pragma unroll
            for (int mi = 0; mi < 4; mi++) qv[mi] = *(const float4*)&sQ[(ty*4+mi)*KSTR + kk];
            #pragma unroll
            for (int ni = 0; ni < 4; ni++) kv[ni] = *(const float4*)&sKV[(tx+32*ni)*KSTR + kk];
            #pragma unroll
            for (int mi = 0; mi < 4; mi++)
                #pragma unroll
                for (int ni = 0; ni < 4; ni++)
                    acc[mi][ni] += qv[mi].x*kv[ni].x + qv[mi].y*kv[ni].y
                                 + qv[mi].z*kv[ni].z + qv[mi].w*kv[ni].w;
        }
        #pragma unroll
        for (int mi = 0; mi < 4; mi++) {
            int mm = ty*4+mi;
            float rs = 0.f;
            #pragma unroll
            for (int ni = 0; ni < 4; ni++) {
                float p = __expf(acc[mi][ni]);
                sP[mm*SNW + t*NTILE + tx + 32*ni] = p;
                rs += p;
            }
            #pragma unroll
            for (int off = 16; off > 0; off >>= 1) rs += __shfl_xor_sync(0xffffffffu, rs, off);
            if (tx == 0) sSum[mm] += rs;
        }
        __syncthreads();
    }
    if (tid < MT) sSum[tid] = 1.0f / sSum[tid];
    __syncthreads();
    #pragma unroll 4
    for (int i = tid; i < MT * 192; i += 256) {
        int mm = i / 192, j4 = (i - mm*192) << 2;
        float4 p = *(const float4*)&sP[mm*SNW + j4];
        float iv = sSum[mm];
        p.x*=iv; p.y*=iv; p.z*=iv; p.w*=iv;
        *(float4*)&Attn[((((size_t)b*SS)+q0+mm)*SH+h)*SNW + j4] = p;
    }
    float acco[4][2];
    #pragma unroll
    for (int mi = 0; mi < 4; mi++) { acco[mi][0]=0.f; acco[mi][1]=0.f; }
    for (int t = 0; t < 6; t++) {
        int ck = c + (t >> 1) - 1, koff = (t & 1) * NTILE;
        bool valid = (ck >= 0) && (ck < SC);
        __syncthreads();
        for (int i = tid; i < NTILE * 16; i += 256) {
            int n = i >> 4, d4 = (i & 15) << 2;
            float4 vv = make_float4(0.f,0.f,0.f,0.f);
            if (valid) vv = *(const float4*)&V[((((size_t)b*SS)+ck*256+koff+n)*SH+h)*SD + d4];
            *(float4*)&sKV[n * KSTR + d4] = vv;
        }
        __syncthreads();
        #pragma unroll 8
        for (int kk = 0; kk < NTILE; kk += 4) {
            float4 pv[4];
            #pragma unroll
            for (int mi = 0; mi < 4; mi++) pv[mi] = *(const float4*)&sP[(ty*4+mi)*SNW + t*NTILE + kk];
            #pragma unroll
            for (int u = 0; u < 4; u++) {
                float va0 = sKV[(kk+u)*KSTR + tx], va1 = sKV[(kk+u)*KSTR + tx + 32];
                #pragma unroll
                for (int mi = 0; mi < 4; mi++) {
                    float pm = (u==0)?pv[mi].x:(u==1)?pv[mi].y:(u==2)?pv[mi].z:pv[mi].w;
                    acco[mi][0] += pm*va0;
                    acco[mi][1] += pm*va1;
                }
            }
        }
    }
    #pragma unroll
    for (int mi = 0; mi < 4; mi++) {
        int mm = ty*4+mi;
        float iv = sSum[mm];
        float* op = &Out[((((size_t)b*SS)+q0+mm)*SH+h)*SD];
        op[tx] = acco[mi][0]*iv;
        op[tx+32] = acco[mi][1]*iv;
    }
}

extern "C" void kernel_launch(void* const* d_in, const int* in_sizes, int n_in,
                              void* d_out, int out_size)
{
    const float* q = (const float*)d_in[0];
    const float* k = (const float*)d_in[1];
    const float* v = (const float*)d_in[2];
    float* out  = (float*)d_out;
    float* attn = out + (size_t)SB * SS * SH * SD;   // [output | attention]

    cudaFuncAttributes fa{};
    cudaFuncGetAttributes(&fa, wk_tc);
    if (fa.numRegs >= 40) {
        cudaFuncSetAttribute(wk_tc, cudaFuncAttributeMaxDynamicSharedMemorySize, SMEM_TC);
        wk_tc<<<SB * SC * SH * 2, 256, SMEM_TC>>>(q, k, v, out, attn);
    } else {
        const int smem = SMEM_FLOATS * sizeof(float);
        cudaFuncSetAttribute(wk_simt, cudaFuncAttributeMaxDynamicSharedMemorySize, smem);
        wk_simt<<<SB * SC * SH * 8, 256, smem>>>(q, k, v, out, attn);
    }
}

// round 13
// speedup vs baseline: 1.8283x; 1.0268x over previous
#include <cuda_runtime.h>
#include <cuda_bf16.h>
#include <cuda_fp16.h>
#include <cstdint>

#define SB 2
#define SS 8192
#define SH 8
#define SD 64
#define SC 32
#define SNW 768

#if defined(__CUDA_ARCH_FEAT_SM103_ALL) || defined(__CUDA_ARCH_FEAT_SM100_ALL) || \
    defined(__CUDA_ARCH_FEAT_SM101_ALL) || defined(__CUDA_ARCH_FEAT_SM110_ALL)
#define HAS_TC 1
#else
#define HAS_TC 0
#endif

// smem layout (bytes)
#define OFF_MBQ   8
#define OFF_MBP   16
#define OFF_RS    64       /* 4 partials x 128 rows x 4B = 2048 */
#define OFF_INV   2112
#define OFF_QHI   4096
#define OFF_QLO   20480
#define OFF_KHI   36864
#define OFF_KLO   53248
#define OFF_VHI   69632    /* fp16 V^T: 16KB */
#define OFF_PHI   86016    /* fp16 P: 32KB */
#define SMEM_TC   118784

#define IDESC_QK 0x08200490u   /* M=128 N=128, bf16 inputs */
#define IDESC_PV 0x08100010u   /* M=128 N=64,  fp16 inputs */

#if HAS_TC
__device__ __forceinline__ uint32_t smem_u32(const void* p) {
    uint32_t a;
    asm("{ .reg .u64 t; cvta.to.shared.u64 t, %1; cvt.u32.u64 %0, t; }" : "=r"(a) : "l"(p));
    return a;
}
__device__ __forceinline__ uint32_t elect1() {
    uint32_t p;
    asm volatile("{ .reg .pred p; elect.sync _|p, 0xFFFFFFFF; selp.b32 %0, 1, 0, p; }" : "=r"(p));
    return p;
}
__device__ __forceinline__ uint64_t desc_k(uint32_t a) {   // K-major SW128: LBO=1, SBO=64
    return (2ull << 61) | (1ull << 46) | (64ull << 32) | (1ull << 16) | ((a >> 4) & 0x3FFF);
}
__device__ __forceinline__ void mma_ss(uint32_t d, uint64_t a, uint64_t b, uint32_t id, uint32_t en) {
    asm volatile(
        "{\n\t.reg .pred p;\n\tsetp.ne.u32 p, %4, 0;\n\t"
        "tcgen05.mma.cta_group::1.kind::f16 [%0], %1, %2, %3, {%5, %5, %5, %5}, p;\n\t}"
        :: "r"(d), "l"(a), "l"(b), "r"(id), "r"(en), "r"(0u) : "memory");
}
#define TM_FENCE_A() asm volatile("tcgen05.fence::after_thread_sync;" ::: "memory")
#define TM_FENCE_B() asm volatile("tcgen05.fence::before_thread_sync;" ::: "memory")
#define TM_WAIT_LD() asm volatile("tcgen05.wait::ld.sync.aligned;" ::: "memory")
#define FENCE_ASYNC() asm volatile("fence.proxy.async.shared::cta;" ::: "memory")
#define COMMIT(mb) asm volatile("tcgen05.commit.cta_group::1.mbarrier::arrive::one.shared::cluster.b64 [%0];" :: "r"(mb) : "memory")

#define MBAR_WAIT(mb, pa) do {                                                            \
    asm volatile("{\n\t.reg .pred P1;\n\t"                                                \
        "WL%=:\n\t"                                                                       \
        "mbarrier.try_wait.parity.acquire.cta.shared::cta.b64 P1, [%0], %1, 0x989680;\n\t"\
        "@P1 bra.uni WD%=;\n\t"                                                           \
        "bra.uni WL%=;\n\t"                                                               \
        "WD%=:\n\t}" :: "r"(mb), "r"(pa) : "memory");                                     \
} while (0)

#define LDTM_X32(r, a)                                                                    \
    asm volatile("tcgen05.ld.sync.aligned.32x32b.x32.b32 "                                \
        "{%0, %1, %2, %3, %4, %5, %6, %7, %8, %9, %10, %11, %12, %13, %14, %15, "         \
        " %16, %17, %18, %19, %20, %21, %22, %23, %24, %25, %26, %27, %28, %29, %30, %31}, [%32];" \
        : "=r"((r)[0]),  "=r"((r)[1]),  "=r"((r)[2]),  "=r"((r)[3]),                      \
          "=r"((r)[4]),  "=r"((r)[5]),  "=r"((r)[6]),  "=r"((r)[7]),                      \
          "=r"((r)[8]),  "=r"((r)[9]),  "=r"((r)[10]), "=r"((r)[11]),                     \
          "=r"((r)[12]), "=r"((r)[13]), "=r"((r)[14]), "=r"((r)[15]),                     \
          "=r"((r)[16]), "=r"((r)[17]), "=r"((r)[18]), "=r"((r)[19]),                     \
          "=r"((r)[20]), "=r"((r)[21]), "=r"((r)[22]), "=r"((r)[23]),                     \
          "=r"((r)[24]), "=r"((r)[25]), "=r"((r)[26]), "=r"((r)[27]),                     \
          "=r"((r)[28]), "=r"((r)[29]), "=r"((r)[30]), "=r"((r)[31])                      \
        : "r"(a))

__device__ __forceinline__ void split_pair(float a, float b, uint32_t& hi, uint32_t& lo) {
    uint32_t h;
    asm("cvt.rn.bf16x2.f32 %0, %1, %2;" : "=r"(h) : "f"(b), "f"(a));  // lo16=a, hi16=b
    float fa = __uint_as_float(h << 16);
    float fb = __uint_as_float(h & 0xffff0000u);
    uint32_t l;
    asm("cvt.rn.bf16x2.f32 %0, %1, %2;" : "=r"(l) : "f"(b - fb), "f"(a - fa));
    hi = h; lo = l;
}
__device__ __forceinline__ uint32_t f16x2(float a, float b) {   // lo16=a, hi16=b
    uint32_t r;
    asm("cvt.rn.f16x2.f32 %0, %1, %2;" : "=r"(r) : "f"(b), "f"(a));
    return r;
}

// prefetch 128x64 fp32 tile into 4 float4 regs (coalesced, 512 threads)
__device__ __forceinline__ void ldg4(const float* __restrict__ g, bool valid, int tid, float4* r) {
    #pragma unroll
    for (int it = 0; it < 4; it++) {
        int i = it * 512 + tid;
        int n = i >> 4, e4 = (i & 15) << 2;
        r[it] = valid ? *(const float4*)(g + (size_t)n * (SH * SD) + e4)
                      : make_float4(0.f, 0.f, 0.f, 0.f);
    }
}
// regs -> bf16 hi/lo, K-major SW128 128B rows (Q and K tiles)
__device__ __forceinline__ void sts_split(const float4* r, char* smc, int offhi, int offlo, int tid) {
    #pragma unroll
    for (int it = 0; it < 4; it++) {
        int i = it * 512 + tid;
        int n = i >> 4, e4 = (i & 15) << 2;
        uint32_t h0, l0, h1, l1;
        split_pair(r[it].x, r[it].y, h0, l0);
        split_pair(r[it].z, r[it].w, h1, l1);
        int boff = n * 128 + e4 * 2;
        int sw = boff ^ ((boff >> 3) & 0x70);
        *(uint2*)(smc + offhi + sw) = make_uint2(h0, h1);
        *(uint2*)(smc + offlo + sw) = make_uint2(l0, l1);
    }
}
// V regs [tok][dim] -> V^T fp16, blocked-atom K-major (atom=8x64, 8 atom-rows)
__device__ __forceinline__ void sts_vt(const float4* r, char* smc, int tid) {
    #pragma unroll
    for (int it = 0; it < 4; it++) {
        int i = it * 512 + tid;
        int n = i >> 4, e4 = (i & 15) << 2;
        float vals[4] = {r[it].x, r[it].y, r[it].z, r[it].w};
        #pragma unroll
        for (int j = 0; j < 4; j++) {
            int e = e4 + j;
            unsigned short hv;
            asm("{ .reg .f16 t; cvt.rn.f16.f32 t, %1; mov.b16 %0, t; }"
                : "=h"(hv) : "f"(vals[j]));
            int atom = (e >> 3) + ((n >> 6) << 3);
            int boff = atom * 1024 + (e & 7) * 128 + (n & 63) * 2;
            int sw = boff ^ ((boff >> 3) & 0x70);
            *(unsigned short*)(smc + OFF_VHI + sw) = hv;
        }
    }
}

__device__ __forceinline__ void issue_qk(uint32_t smb, uint32_t tS) {
    uint64_t aQh = desc_k(smb + OFF_QHI), aQl = desc_k(smb + OFF_QLO);
    uint64_t bKh = desc_k(smb + OFF_KHI), bKl = desc_k(smb + OFF_KLO);
    uint64_t as[3] = {aQh, aQh, aQl};
    uint64_t bs[3] = {bKh, bKl, bKh};
    uint32_t en = 0;
    #pragma unroll
    for (int tt = 0; tt < 3; tt++)
        #pragma unroll
        for (int k = 0; k < 4; k++) { mma_ss(tS, as[tt] + 2 * k, bs[tt] + 2 * k, IDESC_QK, en); en = 1; }
    COMMIT(smb + OFF_MBQ);
}
// single-term fp16 PV: O += P(fp16) @ V^T(fp16)
__device__ __forceinline__ void issue_pv(uint32_t smb, uint32_t tO, uint32_t en0) {
    uint64_t aP = desc_k(smb + OFF_PHI);
    uint64_t bV = desc_k(smb + OFF_VHI);
    uint32_t en = en0;
    #pragma unroll
    for (int k = 0; k < 8; k++) {
        mma_ss(tO, aP + (k >> 2) * 1024 + (k & 3) * 2,
                   bV + (k >> 2) * 512  + (k & 3) * 2, IDESC_PV, en);
        en = 1;
    }
    COMMIT(smb + OFF_MBP);
}
#endif  // HAS_TC

__global__ void __launch_bounds__(512, 1)
wk_tc(const float* __restrict__ Q, const float* __restrict__ K,
      const float* __restrict__ V, float* __restrict__ Out, float* __restrict__ Attn)
{
#if HAS_TC
    extern __shared__ char smc[];
    const uint32_t smb = smem_u32(smc);
    const int tid = threadIdx.x;
    const int w = tid >> 5, lane = tid & 31;
    const int sp = w & 3, ch = w >> 2;          // ch in 0..3: 32-col chunk
    const int m = sp * 32 + lane;

    const int blk = blockIdx.x;
    const int mh = blk & 1, h = (blk >> 1) & 7, c = (blk >> 4) & 31, b = blk >> 9;
    const int q0 = c * 256 + mh * 128;

    if (w == 0) {
        asm volatile("tcgen05.alloc.cta_group::1.sync.aligned.shared::cta.b32 [%0], %1;"
                     :: "r"(smb), "r"(512) : "memory");
        asm volatile("tcgen05.relinquish_alloc_permit.cta_group::1.sync.aligned;");
    }
    if (tid == 0) {
        asm volatile("mbarrier.init.shared.b64 [%0], %1;" :: "r"(smb + OFF_MBQ), "r"(1) : "memory");
        asm volatile("mbarrier.init.shared.b64 [%0], %1;" :: "r"(smb + OFF_MBP), "r"(1) : "memory");
    }
    __syncthreads();
    uint32_t tmem;
    asm volatile("ld.shared.b32 %0, [%1];" : "=r"(tmem) : "r"(smb));
    const uint32_t tS0 = tmem, tS1 = tmem + 128, tO = tmem + 256;

    // Q tile resident all kernel
    {
        float4 qr[4];
        ldg4(Q + ((size_t)(b * SS + q0) * SH + h) * SD, true, tid, qr);
        sts_split(qr, smc, OFF_QHI, OFF_QLO, tid);
    }

    auto kvalid = [&](int t) { int ck = c + (t >> 1) - 1; return (ck >= 0) && (ck < SC); };
    auto kvoff = [&](int t) -> size_t {
        int ck = c + (t >> 1) - 1;
        return ((size_t)(b * SS + ck * 256 + (t & 1) * 128) * SH + h) * SD;
    };

    int phQ = 0, phP = 0;
    float rsum = 0.f;
    float4 kreg[4], vreg[4];

    // ================= pass A: rowsums =================
    ldg4(K + kvoff(0), kvalid(0), tid, kreg);
    sts_split(kreg, smc, OFF_KHI, OFF_KLO, tid);
    FENCE_ASYNC();
    __syncthreads();
    if (w == 0 && elect1()) { TM_FENCE_A(); issue_qk(smb, tS0); }
    ldg4(K + kvoff(1), kvalid(1), tid, kreg);

    for (int t = 0; t < 6; t++) {
        MBAR_WAIT(smb + OFF_MBQ, phQ & 1); phQ++;     // QK_t done
        TM_FENCE_A();
        if (t < 5) {
            sts_split(kreg, smc, OFF_KHI, OFF_KLO, tid);   // K_{t+1} (K buf free)
            FENCE_ASYNC();
        }
        __syncthreads();
        if (t < 5 && w == 0 && elect1()) { TM_FENCE_A(); issue_qk(smb, ((t + 1) & 1) ? tS1 : tS0); }
        if (t < 4) ldg4(K + kvoff(t + 2), kvalid(t + 2), tid, kreg);

        const uint32_t tS = (t & 1) ? tS1 : tS0;
        {
            uint32_t r[32];
            LDTM_X32(r, tS + ch * 32);
            TM_WAIT_LD();
            #pragma unroll
            for (int q = 0; q < 32; q++) rsum += __expf(__uint_as_float(r[q]));
        }
        TM_FENCE_B();
    }
    // after pass A: tS0 holds S_4, tS1 holds S_5 (reused in pass B steps 0,1)

    // rowsum combine (4 column-chunk partials) -> inv
    *(float*)(smc + OFF_RS + (ch * 128 + m) * 4) = rsum;
    __syncthreads();
    if (tid < 128) {
        float s = *(float*)(smc + OFF_RS + tid * 4)
                + *(float*)(smc + OFF_RS + (128 + tid) * 4)
                + *(float*)(smc + OFF_RS + (256 + tid) * 4)
                + *(float*)(smc + OFF_RS + (384 + tid) * 4);
        *(float*)(smc + OFF_INV + tid * 4) = 1.0f / s;
    }
    __syncthreads();
    const float inv = *(float*)(smc + OFF_INV + m * 4);

    // ================= pass B: tiles in order {4,5,0,1,2,3} =================
    ldg4(V + kvoff(4), kvalid(4), tid, vreg);          // V for step 0
    const int tmap[6] = {4, 5, 0, 1, 2, 3};

    #pragma unroll
    for (int i = 0; i < 6; i++) {
        const int t = tmap[i];
        if (i > 0) { MBAR_WAIT(smb + OFF_MBP, phP & 1); phP++; TM_FENCE_A(); }  // PV_{i-1}
        sts_vt(vreg, smc, tid);                        // V_t (V buf + PHI free)
        if (i < 4) ldg4(K + kvoff(tmap[i + 2]), kvalid(tmap[i + 2]), tid, kreg);
        if (i == 5) { MBAR_WAIT(smb + OFF_MBQ, phQ & 1); phQ++; TM_FENCE_A(); } // QK_{tmap[5]}

        const uint32_t tS = (i & 1) ? tS1 : tS0;
        {
            uint32_t r[32];
            LDTM_X32(r, tS + ch * 32);
            TM_WAIT_LD();
            float p[32];
            #pragma unroll
            for (int q = 0; q < 32; q++) p[q] = __expf(__uint_as_float(r[q])) * inv;
            #pragma unroll
            for (int q = 0; q < 8; q++) {
                int col = ch * 32 + q * 4;
                uint32_t h0 = f16x2(p[4*q],   p[4*q+1]);
                uint32_t h1 = f16x2(p[4*q+2], p[4*q+3]);
                int atom = (m >> 3) + ((col >> 6) << 4);
                int boff = atom * 1024 + (m & 7) * 128 + (col & 63) * 2;
                int sw = boff ^ ((boff >> 3) & 0x70);
                *(uint2*)(smc + OFF_PHI + sw) = make_uint2(h0, h1);
            }
        }
        TM_FENCE_B();
        FENCE_ASYNC();
        __syncthreads();                               // PHI (all warps) + V complete
        if (w == 0 && elect1()) { TM_FENCE_A(); issue_pv(smb, tO, i > 0); }

        // attn write from PHI fp16 (overlaps PV_i); warp w -> rows w*8..+7, lane -> col lane*4
        {
            float* abase = Attn + ((size_t)(b * SS + q0) * SH + h) * SNW + t * 128;
            const int col = lane * 4;
            const int atomc = (col >> 6) << 4;
            #pragma unroll
            for (int it2 = 0; it2 < 8; it2++) {
                int row = w * 8 + it2;
                int atom = (row >> 3) + atomc;
                int boff = atom * 1024 + (row & 7) * 128 + (col & 63) * 2;
                int sw = boff ^ ((boff >> 3) & 0x70);
                uint2 hv = *(uint2*)(smc + OFF_PHI + sw);
                float2 f0 = __half22float2(*(__half2*)&hv.x);
                float2 f1 = __half22float2(*(__half2*)&hv.y);
                *(float4*)(abase + (size_t)row * (SH * SNW) + col) =
                    make_float4(f0.x, f0.y, f1.x, f1.y);
            }
        }
        if (i < 4) {
            if (i >= 1) { MBAR_WAIT(smb + OFF_MBQ, phQ & 1); phQ++; TM_FENCE_A(); } // QK_{tmap[i+1]} done
            sts_split(kreg, smc, OFF_KHI, OFF_KLO, tid);   // K_{tmap[i+2]}
        }
        if (i < 5) ldg4(V + kvoff(tmap[i + 1]), kvalid(tmap[i + 1]), tid, vreg);
        if (i < 4) {
            FENCE_ASYNC();
            __syncthreads();
            if (w == 0 && elect1()) { TM_FENCE_A(); issue_qk(smb, (i & 1) ? tS1 : tS0); }
        }
    }
    MBAR_WAIT(smb + OFF_MBP, phP & 1); phP++;          // PV_5
    TM_FENCE_A();

    // O epilogue (already normalized): warps with ch<2 cover the 64 cols
    if (ch < 2) {
        uint32_t r[32];
        LDTM_X32(r, tO + ch * 32);
        TM_WAIT_LD();
        TM_FENCE_B();
        float* orow = Out + ((size_t)(b * SS + q0 + m) * SH + h) * SD + ch * 32;
        #pragma unroll
        for (int q = 0; q < 8; q++)
            *(float4*)(orow + q * 4) = make_float4(
                __uint_as_float(r[4*q]),   __uint_as_float(r[4*q+1]),
                __uint_as_float(r[4*q+2]), __uint_as_float(r[4*q+3]));
    }
    __syncthreads();
    if (tid == 0) {
        asm volatile("mbarrier.inval.shared.b64 [%0];" :: "r"(smb + OFF_MBQ) : "memory");
        asm volatile("mbarrier.inval.shared.b64 [%0];" :: "r"(smb + OFF_MBP) : "memory");
    }
    __syncthreads();
    if (w == 0)
        asm volatile("tcgen05.dealloc.cta_group::1.sync.aligned.b32 %0, %1;" :: "r"(tmem), "r"(512));
#endif  // HAS_TC
}

// ================= SIMT fallback =================
#define MT 32
#define NTILE 128
#define KSTR 68
#define SMEM_FLOATS (MT*SNW + MT*KSTR + NTILE*KSTR + MT)

__global__ void __launch_bounds__(256, 1)
wk_simt(const float* __restrict__ Q, const float* __restrict__ K,
        const float* __restrict__ V, float* __restrict__ Out, float* __restrict__ Attn)
{
    extern __shared__ float sm[];
    float* sP = sm;
    float* sQ = sP + MT * SNW;
    float* sKV = sQ + MT * KSTR;
    float* sSum = sKV + NTILE * KSTR;
    const int tid = threadIdx.x, tx = tid & 31, ty = tid >> 5;
    const int blk = blockIdx.x;
    const int mblk = blk & 7, h = (blk >> 3) & 7, c = (blk >> 6) & 31, b = blk >> 11;
    const int q0 = c * 256 + mblk * MT;
    if (tid < MT) sSum[tid] = 0.0f;
    for (int i = tid; i < MT * 16; i += 256) {
        int mm = i >> 4, d4 = (i & 15) << 2;
        *(float4*)&sQ[mm * KSTR + d4] = *(const float4*)&Q[((((size_t)b*SS)+q0+mm)*SH+h)*SD + d4];
    }
    for (int t = 0; t < 6; t++) {
        int ck = c + (t >> 1) - 1, koff = (t & 1) * NTILE;
        bool valid = (ck >= 0) && (ck < SC);
        for (int i = tid; i < NTILE * 16; i += 256) {
            int n = i >> 4, d4 = (i & 15) << 2;
            float4 kv = make_float4(0.f,0.f,0.f,0.f);
            if (valid) kv = *(const float4*)&K[((((size_t)b*SS)+ck*256+koff+n)*SH+h)*SD + d4];
            *(float4*)&sKV[n * KSTR + d4] = kv;
        }
        __syncthreads();
        float acc[4][4];
        #pragma unroll
        for (int mi = 0; mi < 4; mi++) { acc[mi][0]=acc[mi][1]=acc[mi][2]=acc[mi][3]=0.f; }
        #pragma unroll
        for (int kk = 0; kk < SD; kk += 4) {
            float4 qv[4], kv[4];
            #pragma unroll
            for (int mi = 0; mi < 4; mi++) qv[mi] = *(const float4*)&sQ[(ty*4+mi)*KSTR + kk];
            #pragma unroll
            for (int ni = 0; ni < 4; ni++) kv[ni] = *(const float4*)&sKV[(tx+32*ni)*KSTR + kk];
            #pragma unroll
            for (int mi = 0; mi < 4; mi++)
                #pragma unroll
                for (int ni = 0; ni < 4; ni++)
                    acc[mi][ni] += qv[mi].x*kv[ni].x + qv[mi].y*kv[ni].y
                                 + qv[mi].z*kv[ni].z + qv[mi].w*kv[ni].w;
        }
        #pragma unroll
        for (int mi = 0; mi < 4; mi++) {
            int mm = ty*4+mi;
            float rs = 0.f;
            #pragma unroll
            for (int ni = 0; ni < 4; ni++) {
                float p = __expf(acc[mi][ni]);
                sP[mm*SNW + t*NTILE + tx + 32*ni] = p;
                rs += p;
            }
            #pragma unroll
            for (int off = 16; off > 0; off >>= 1) rs += __shfl_xor_sync(0xffffffffu, rs, off);
            if (tx == 0) sSum[mm] += rs;
        }
        __syncthreads();
    }
    if (tid < MT) sSum[tid] = 1.0f / sSum[tid];
    __syncthreads();
    #pragma unroll 4
    for (int i = tid; i < MT * 192; i += 256) {
        int mm = i / 192, j4 = (i - mm*192) << 2;
        float4 p = *(const float4*)&sP[mm*SNW + j4];
        float iv = sSum[mm];
        p.x*=iv; p.y*=iv; p.z*=iv; p.w*=iv;
        *(float4*)&Attn[((((size_t)b*SS)+q0+mm)*SH+h)*SNW + j4] = p;
    }
    float acco[4][2];
    #pragma unroll
    for (int mi = 0; mi < 4; mi++) { acco[mi][0]=0.f; acco[mi][1]=0.f; }
    for (int t = 0; t < 6; t++) {
        int ck = c + (t >> 1) - 1, koff = (t & 1) * NTILE;
        bool valid = (ck >= 0) && (ck < SC);
        __syncthreads();
        for (int i = tid; i < NTILE * 16; i += 256) {
            int n = i >> 4, d4 = (i & 15) << 2;
            float4 vv = make_float4(0.f,0.f,0.f,0.f);
            if (valid) vv = *(const float4*)&V[((((size_t)b*SS)+ck*256+koff+n)*SH+h)*SD + d4];
            *(float4*)&sKV[n * KSTR + d4] = vv;
        }
        __syncthreads();
        #pragma unroll 8
        for (int kk = 0; kk < NTILE; kk += 4) {
            float4 pv[4];
            #pragma unroll
            for (int mi = 0; mi < 4; mi++) pv[mi] = *(const float4*)&sP[(ty*4+mi)*SNW + t*NTILE + kk];
            #pragma unroll
            for (int u = 0; u < 4; u++) {
                float va0 = sKV[(kk+u)*KSTR + tx], va1 = sKV[(kk+u)*KSTR + tx + 32];
                #pragma unroll
                for (int mi = 0; mi < 4; mi++) {
                    float pm = (u==0)?pv[mi].x:(u==1)?pv[mi].y:(u==2)?pv[mi].z:pv[mi].w;
                    acco[mi][0] += pm*va0;
                    acco[mi][1] += pm*va1;
                }
            }
        }
    }
    #pragma unroll
    for (int mi = 0; mi < 4; mi++) {
        int mm = ty*4+mi;
        float iv = sSum[mm];
        float* op = &Out[((((size_t)b*SS)+q0+mm)*SH+h)*SD];
        op[tx] = acco[mi][0]*iv;
        op[tx+32] = acco[mi][1]*iv;
    }
}

extern "C" void kernel_launch(void* const* d_in, const int* in_sizes, int n_in,
                              void* d_out, int out_size)
{
    const float* q = (const float*)d_in[0];
    const float* k = (const float*)d_in[1];
    const float* v = (const float*)d_in[2];
    float* out  = (float*)d_out;
    float* attn = out + (size_t)SB * SS * SH * SD;   // [output | attention]

    cudaFuncAttributes fa{};
    cudaFuncGetAttributes(&fa, wk_tc);
    if (fa.numRegs >= 40) {
        cudaFuncSetAttribute(wk_tc, cudaFuncAttributeMaxDynamicSharedMemorySize, SMEM_TC);
        wk_tc<<<SB * SC * SH * 2, 512, SMEM_TC>>>(q, k, v, out, attn);
    } else {
        const int smem = SMEM_FLOATS * sizeof(float);
        cudaFuncSetAttribute(wk_simt, cudaFuncAttributeMaxDynamicSharedMemorySize, smem);
        wk_simt<<<SB * SC * SH * 8, 256, smem>>>(q, k, v, out, attn);
    }
}